// round 1
// baseline (speedup 1.0000x reference)
#include <cuda_runtime.h>
#include <math.h>

#define Bsz  8
#define Cch  1024
#define Tlen 4096
#define Hh   16
#define Dd   64
#define C3   3072

// Scratch (allocation-free): qkv GEMM output (later reused for attention output),
// and the dwconv+norm output.
__device__ float g_qkv[(size_t)Bsz * C3 * Tlen];
__device__ float g_conv[(size_t)Bsz * C3 * Tlen];

// ---------------------------------------------------------------------------
// SGEMM: C[b] = A[M,K] @ B[b][K,N] + bias, all row-major fp32.
// 128x128 block, BK=8, 256 threads, 8x8 per thread.
// ---------------------------------------------------------------------------
__global__ __launch_bounds__(256) void sgemm_bias(
    const float* __restrict__ A, const float* __restrict__ Bm,
    const float* __restrict__ bias, float* __restrict__ Cm,
    int M, int N, int K, size_t strideB, size_t strideC)
{
    __shared__ float As[8][128];
    __shared__ float Bs[8][128];

    const float* Bb = Bm + (size_t)blockIdx.z * strideB;
    float*       Cb = Cm + (size_t)blockIdx.z * strideC;
    const int rowBase = blockIdx.y * 128;
    const int colBase = blockIdx.x * 128;

    const int tid = threadIdx.x;
    const int tx = tid & 15;        // 0..15 -> col groups of 8
    const int ty = tid >> 4;        // 0..15 -> row groups of 8

    const int arow = tid >> 1;          // 0..127
    const int ak   = (tid & 1) * 4;     // 0 or 4
    const int bkk  = tid >> 5;          // 0..7
    const int bcol = (tid & 31) * 4;    // 0..124

    const float* Aptr = A  + (size_t)(rowBase + arow) * K + ak;
    const float* Bptr = Bb + (size_t)bkk * N + colBase + bcol;

    float acc[8][8];
#pragma unroll
    for (int i = 0; i < 8; i++)
#pragma unroll
        for (int j = 0; j < 8; j++) acc[i][j] = 0.f;

    for (int k0 = 0; k0 < K; k0 += 8) {
        float4 av = *(const float4*)(Aptr + k0);
        float4 bv = *(const float4*)(Bptr + (size_t)k0 * N);
        As[ak + 0][arow] = av.x;
        As[ak + 1][arow] = av.y;
        As[ak + 2][arow] = av.z;
        As[ak + 3][arow] = av.w;
        *(float4*)&Bs[bkk][bcol] = bv;
        __syncthreads();

#pragma unroll
        for (int kk = 0; kk < 8; kk++) {
            float4 a0 = *(float4*)&As[kk][ty * 8];
            float4 a1 = *(float4*)&As[kk][ty * 8 + 4];
            float4 b0 = *(float4*)&Bs[kk][tx * 8];
            float4 b1 = *(float4*)&Bs[kk][tx * 8 + 4];
            float aa[8] = {a0.x, a0.y, a0.z, a0.w, a1.x, a1.y, a1.z, a1.w};
            float bb[8] = {b0.x, b0.y, b0.z, b0.w, b1.x, b1.y, b1.z, b1.w};
#pragma unroll
            for (int i = 0; i < 8; i++)
#pragma unroll
                for (int j = 0; j < 8; j++)
                    acc[i][j] += aa[i] * bb[j];
        }
        __syncthreads();
    }

#pragma unroll
    for (int i = 0; i < 8; i++) {
        int row = rowBase + ty * 8 + i;
        float bsv = bias[row];
        float* cp = Cb + (size_t)row * N + colBase + tx * 8;
        float4 c0 = make_float4(acc[i][0] + bsv, acc[i][1] + bsv,
                                acc[i][2] + bsv, acc[i][3] + bsv);
        float4 c1 = make_float4(acc[i][4] + bsv, acc[i][5] + bsv,
                                acc[i][6] + bsv, acc[i][7] + bsv);
        *(float4*)cp       = c0;
        *(float4*)(cp + 4) = c1;
    }
}

// ---------------------------------------------------------------------------
// Depthwise conv3 (pad 1) + bias + L2-normalize over T (q,k channels only).
// One block per (b, ch) row of 4096 contiguous floats.
// ---------------------------------------------------------------------------
__global__ __launch_bounds__(256) void conv_norm_kernel(
    const float* __restrict__ in, const float* __restrict__ w_dw,
    const float* __restrict__ b_dw, float* __restrict__ out)
{
    __shared__ __align__(16) float s[Tlen + 8];   // data at s[4..4+Tlen), halos s[3], s[4+Tlen]
    __shared__ float red[8];

    const int row = blockIdx.x;          // b*C3 + ch
    const int ch  = row % C3;
    const float* inr  = in  + (size_t)row * Tlen;
    float*       outr = out + (size_t)row * Tlen;
    const int tid = threadIdx.x;

    if (tid == 0) { s[3] = 0.f; s[4 + Tlen] = 0.f; }
#pragma unroll
    for (int j = 0; j < 4; j++) {
        int t4 = tid + j * 256;
        *(float4*)&s[4 + t4 * 4] = *(const float4*)(inr + t4 * 4);
    }
    __syncthreads();

    const float w0 = w_dw[ch * 3 + 0];
    const float w1 = w_dw[ch * 3 + 1];
    const float w2 = w_dw[ch * 3 + 2];
    const float bb = b_dw[ch];

    float vals[16];
    float ss = 0.f;
#pragma unroll
    for (int j = 0; j < 4; j++) {
        int t = (tid + j * 256) * 4;
#pragma unroll
        for (int i = 0; i < 4; i++) {
            float v = w0 * s[3 + t + i] + w1 * s[4 + t + i] + w2 * s[5 + t + i] + bb;
            vals[j * 4 + i] = v;
            ss += v * v;
        }
    }

    float scale = 1.f;
    if (ch < 2 * Cch) {   // q and k channels get L2-normalized over T
#pragma unroll
        for (int o = 16; o > 0; o >>= 1) ss += __shfl_xor_sync(0xffffffffu, ss, o);
        if ((tid & 31) == 0) red[tid >> 5] = ss;
        __syncthreads();
        if (tid < 32) {
            float r = (tid < 8) ? red[tid] : 0.f;
#pragma unroll
            for (int o = 4; o > 0; o >>= 1) r += __shfl_xor_sync(0xffffffffu, r, o);
            if (tid == 0) red[0] = r;
        }
        __syncthreads();
        float n = sqrtf(red[0]);
        scale = 1.f / fmaxf(n, 1e-12f);
    }

#pragma unroll
    for (int j = 0; j < 4; j++) {
        int t = (tid + j * 256) * 4;
        float4 o4 = make_float4(vals[j * 4 + 0] * scale, vals[j * 4 + 1] * scale,
                                vals[j * 4 + 2] * scale, vals[j * 4 + 3] * scale);
        *(float4*)(outr + t) = o4;
    }
}

// ---------------------------------------------------------------------------
// Cross-covariance attention: per (b,h): A = (q @ k^T) * temp[h]; softmax rows;
// out = A @ v.  q,k,v are [64, T] row-major slices of the conv buffer.
// One block per (b,h), 256 threads, 4x4 micro-tiles.
// ---------------------------------------------------------------------------
__global__ __launch_bounds__(256) void attn_kernel(
    const float* __restrict__ conv, const float* __restrict__ temp,
    float* __restrict__ out)
{
    __shared__ float smA[64][65];   // q tile, then attention matrix
    __shared__ float smB[64][65];   // k tile, then v tile

    const int bh = blockIdx.x;
    const int b = bh >> 4, h = bh & 15;
    const float* qp = conv + ((size_t)b * C3 + h * Dd) * Tlen;
    const float* kp = qp + (size_t)Cch * Tlen;
    const float* vp = qp + (size_t)2 * Cch * Tlen;
    float*       op = out + ((size_t)b * Cch + h * Dd) * Tlen;

    const int tid = threadIdx.x;
    const int tx = tid & 15, ty = tid >> 4;

    float acc[4][4];
#pragma unroll
    for (int i = 0; i < 4; i++)
#pragma unroll
        for (int j = 0; j < 4; j++) acc[i][j] = 0.f;

    // Phase 1: logits A[c][e] = sum_t q[c,t] k[e,t]
    for (int t0 = 0; t0 < Tlen; t0 += 64) {
        for (int i = tid; i < 64 * 16; i += 256) {
            int r = i >> 4;
            int c = (i & 15) << 2;
            float4 qv = *(const float4*)(qp + (size_t)r * Tlen + t0 + c);
            float4 kv = *(const float4*)(kp + (size_t)r * Tlen + t0 + c);
            smA[r][c] = qv.x; smA[r][c + 1] = qv.y; smA[r][c + 2] = qv.z; smA[r][c + 3] = qv.w;
            smB[r][c] = kv.x; smB[r][c + 1] = kv.y; smB[r][c + 2] = kv.z; smB[r][c + 3] = kv.w;
        }
        __syncthreads();
#pragma unroll 16
        for (int kk = 0; kk < 64; kk++) {
            float a[4], bv[4];
#pragma unroll
            for (int i = 0; i < 4; i++) a[i]  = smA[ty * 4 + i][kk];
#pragma unroll
            for (int j = 0; j < 4; j++) bv[j] = smB[tx * 4 + j][kk];
#pragma unroll
            for (int i = 0; i < 4; i++)
#pragma unroll
                for (int j = 0; j < 4; j++)
                    acc[i][j] += a[i] * bv[j];
        }
        __syncthreads();
    }

    // logits * temp into smA, then row softmax
    const float tsc = temp[h];
#pragma unroll
    for (int i = 0; i < 4; i++)
#pragma unroll
        for (int j = 0; j < 4; j++)
            smA[ty * 4 + i][tx * 4 + j] = acc[i][j] * tsc;
    __syncthreads();

    if (tid < 64) {
        float m = -1e30f;
#pragma unroll 8
        for (int e = 0; e < 64; e++) m = fmaxf(m, smA[tid][e]);
        float ssum = 0.f;
#pragma unroll 8
        for (int e = 0; e < 64; e++) {
            float ex = __expf(smA[tid][e] - m);
            smA[tid][e] = ex;
            ssum += ex;
        }
        float inv = 1.f / ssum;
#pragma unroll 8
        for (int e = 0; e < 64; e++) smA[tid][e] *= inv;
    }
    __syncthreads();

    // Phase 2: out[c, t] = sum_e A[c,e] v[e,t]
    for (int t0 = 0; t0 < Tlen; t0 += 64) {
        for (int i = tid; i < 64 * 16; i += 256) {
            int r = i >> 4;
            int c = (i & 15) << 2;
            float4 vv = *(const float4*)(vp + (size_t)r * Tlen + t0 + c);
            smB[r][c] = vv.x; smB[r][c + 1] = vv.y; smB[r][c + 2] = vv.z; smB[r][c + 3] = vv.w;
        }
        __syncthreads();

        float o4[4][4];
#pragma unroll
        for (int i = 0; i < 4; i++)
#pragma unroll
            for (int j = 0; j < 4; j++) o4[i][j] = 0.f;

#pragma unroll 16
        for (int e = 0; e < 64; e++) {
            float a[4], bv[4];
#pragma unroll
            for (int i = 0; i < 4; i++) a[i]  = smA[ty * 4 + i][e];
#pragma unroll
            for (int j = 0; j < 4; j++) bv[j] = smB[e][tx * 4 + j];
#pragma unroll
            for (int i = 0; i < 4; i++)
#pragma unroll
                for (int j = 0; j < 4; j++)
                    o4[i][j] += a[i] * bv[j];
        }
#pragma unroll
        for (int i = 0; i < 4; i++) {
            float4 w4 = make_float4(o4[i][0], o4[i][1], o4[i][2], o4[i][3]);
            *(float4*)(op + (size_t)(ty * 4 + i) * Tlen + t0 + tx * 4) = w4;
        }
        __syncthreads();
    }
}

// ---------------------------------------------------------------------------
extern "C" void kernel_launch(void* const* d_in, const int* in_sizes, int n_in,
                              void* d_out, int out_size)
{
    (void)in_sizes; (void)n_in; (void)out_size;
    const float* x     = (const float*)d_in[0];
    const float* w_qkv = (const float*)d_in[1];
    const float* b_qkv = (const float*)d_in[2];
    const float* w_dw  = (const float*)d_in[3];
    const float* b_dw  = (const float*)d_in[4];
    const float* w_out = (const float*)d_in[5];
    const float* b_out = (const float*)d_in[6];
    const float* temp  = (const float*)d_in[7];
    float* out = (float*)d_out;

    float *qkv_buf, *conv_buf;
    cudaGetSymbolAddress((void**)&qkv_buf,  g_qkv);
    cudaGetSymbolAddress((void**)&conv_buf, g_conv);

    // 1) QKV pointwise GEMM: [3072,1024] @ [1024,4096] per batch
    {
        dim3 grid(Tlen / 128, C3 / 128, Bsz);
        sgemm_bias<<<grid, 256>>>(w_qkv, x, b_qkv, qkv_buf,
                                  C3, Tlen, Cch,
                                  (size_t)Cch * Tlen, (size_t)C3 * Tlen);
    }
    // 2) depthwise conv3 + bias + L2 norm over T for q,k
    conv_norm_kernel<<<Bsz * C3, 256>>>(qkv_buf, w_dw, b_dw, conv_buf);

    // 3) cross-covariance attention (writes compact [B, C, T] into g_qkv)
    attn_kernel<<<Bsz * Hh, 256>>>(conv_buf, temp, qkv_buf);

    // 4) output projection: [1024,1024] @ [1024,4096] per batch
    {
        dim3 grid(Tlen / 128, Cch / 128, Bsz);
        sgemm_bias<<<grid, 256>>>(w_out, qkv_buf, b_out, out,
                                  Cch, Tlen, Cch,
                                  (size_t)Cch * Tlen, (size_t)Cch * Tlen);
    }
}

// round 3
// speedup vs baseline: 2.2028x; 2.2028x over previous
#include <cuda_runtime.h>
#include <cuda_bf16.h>
#include <math.h>
#include <stdint.h>

#define Bsz  8
#define Cch  1024
#define Tlen 4096
#define Hh   16
#define Dd   64
#define C3   3072

// ---------------------------------------------------------------------------
// Scratch (allocation-free __device__ globals)
// ---------------------------------------------------------------------------
__device__ float g_qkv[(size_t)Bsz * C3 * Tlen];               // qkv gemm out / attn out
__device__ float g_conv[(size_t)Bsz * C3 * Tlen];              // conv+norm out
__device__ __nv_bfloat16 g_xhi[(size_t)Bsz * Cch * Tlen];      // activation hi
__device__ __nv_bfloat16 g_xlo[(size_t)Bsz * Cch * Tlen];      // activation lo
__device__ __nv_bfloat16 g_whi[(size_t)(C3 + Cch) * Cch];      // weights hi (qkv|out)
__device__ __nv_bfloat16 g_wlo[(size_t)(C3 + Cch) * Cch];      // weights lo

// ---------------------------------------------------------------------------
// PTX helpers (sm_80+ portable: cp.async, ldmatrix, mma.sync bf16)
// ---------------------------------------------------------------------------
__device__ __forceinline__ uint32_t s2u(const void* p) {
    uint32_t a;
    asm("{ .reg .u64 t; cvta.to.shared.u64 t, %1; cvt.u32.u64 %0, t; }"
        : "=r"(a) : "l"(p));
    return a;
}

#define CP_ASYNC16(dst, src) \
    asm volatile("cp.async.ca.shared.global [%0], [%1], 16;" \
                 :: "r"(dst), "l"(src) : "memory")
#define CP_COMMIT() asm volatile("cp.async.commit_group;" ::: "memory")
#define CP_WAIT0()  asm volatile("cp.async.wait_group 0;"  ::: "memory")

#define LDSM_X4(r0, r1, r2, r3, addr) \
    asm volatile("ldmatrix.sync.aligned.m8n8.x4.shared.b16 {%0,%1,%2,%3}, [%4];" \
                 : "=r"(r0), "=r"(r1), "=r"(r2), "=r"(r3) : "r"(addr))
#define LDSM_X2T(r0, r1, addr) \
    asm volatile("ldmatrix.sync.aligned.m8n8.x2.trans.shared.b16 {%0,%1}, [%2];" \
                 : "=r"(r0), "=r"(r1) : "r"(addr))

#define MMA_BF16(d, a, b) \
    asm volatile("mma.sync.aligned.m16n8k16.row.col.f32.bf16.bf16.f32 " \
                 "{%0,%1,%2,%3}, {%4,%5,%6,%7}, {%8,%9}, {%0,%1,%2,%3};" \
                 : "+f"((d)[0]), "+f"((d)[1]), "+f"((d)[2]), "+f"((d)[3]) \
                 : "r"((a)[0]), "r"((a)[1]), "r"((a)[2]), "r"((a)[3]), \
                   "r"((b)[0]), "r"((b)[1]))

// ---------------------------------------------------------------------------
// fp32 -> bf16 hi/lo split conversion (vectorized by 4)
// ---------------------------------------------------------------------------
__global__ __launch_bounds__(256) void cvt_hilo(
    const float* __restrict__ in, __nv_bfloat16* __restrict__ hi,
    __nv_bfloat16* __restrict__ lo, int n4)
{
    int i = blockIdx.x * blockDim.x + threadIdx.x;
    if (i >= n4) return;
    float4 v = ((const float4*)in)[i];
    __nv_bfloat16 h0 = __float2bfloat16(v.x);
    __nv_bfloat16 h1 = __float2bfloat16(v.y);
    __nv_bfloat16 h2 = __float2bfloat16(v.z);
    __nv_bfloat16 h3 = __float2bfloat16(v.w);
    __nv_bfloat16 l0 = __float2bfloat16(v.x - __bfloat162float(h0));
    __nv_bfloat16 l1 = __float2bfloat16(v.y - __bfloat162float(h1));
    __nv_bfloat16 l2 = __float2bfloat16(v.z - __bfloat162float(h2));
    __nv_bfloat16 l3 = __float2bfloat16(v.w - __bfloat162float(h3));
    __nv_bfloat162* hp = (__nv_bfloat162*)hi;
    __nv_bfloat162* lp = (__nv_bfloat162*)lo;
    hp[2 * i]     = __nv_bfloat162(h0, h1);
    hp[2 * i + 1] = __nv_bfloat162(h2, h3);
    lp[2 * i]     = __nv_bfloat162(l0, l1);
    lp[2 * i + 1] = __nv_bfloat162(l2, l3);
}

// ---------------------------------------------------------------------------
// bf16x3 GEMM via mma.sync: C[b] = W[M,1024] @ X[b][1024,4096] + bias
// CTA: 128(M) x 128(N), BK=32, 256 threads (8 warps, each 64x32).
// A smem [128][40] bf16 (pad), B smem [32][136] bf16 (pad). 2-stage cp.async.
// ---------------------------------------------------------------------------
#define GK   1024
#define GN   4096
#define A_HI 0
#define A_LO 10240
#define B_HI 20480
#define B_LO 29184
#define STG  37888
#define GSMEM (2 * STG)

__global__ __launch_bounds__(256) void gemm_mma_bf16x3(
    const __nv_bfloat16* __restrict__ Whi, const __nv_bfloat16* __restrict__ Wlo,
    const __nv_bfloat16* __restrict__ Xhi, const __nv_bfloat16* __restrict__ Xlo,
    const float* __restrict__ bias, float* __restrict__ C, size_t strideC)
{
    extern __shared__ char smem[];
    const uint32_t sb = s2u(smem);
    const int tid  = threadIdx.x;
    const int wid  = tid >> 5;
    const int lane = tid & 31;
    const int wm = wid & 1;              // 0..1 : 64-row slab
    const int wn = wid >> 1;             // 0..3 : 32-col slab
    const int rowBase = blockIdx.y * 128;
    const int colBase = blockIdx.x * 128;
    const size_t bOff = (size_t)blockIdx.z * GK * GN;
    const __nv_bfloat16* xh = Xhi + bOff;
    const __nv_bfloat16* xl = Xlo + bOff;
    float* Cb = C + (size_t)blockIdx.z * strideC;

    // per-thread load coordinates (8 x 16B cp.async per stage)
    int a_hl[4], a_row[4], a_kq[4], b_hl[4], b_row[4], b_nq[4];
#pragma unroll
    for (int i = 0; i < 4; i++) {
        int u = tid + i * 256;
        a_hl[i] = u >> 9;  int v = u & 511;
        a_row[i] = v >> 2; a_kq[i] = v & 3;
        b_hl[i] = u >> 9;
        b_row[i] = v >> 4; b_nq[i] = v & 15;
    }

    auto load_stage = [&](int c, int st) {
        const uint32_t so = sb + st * STG;
        const int k0 = c * 32;
#pragma unroll
        for (int i = 0; i < 4; i++) {
            const __nv_bfloat16* src = (a_hl[i] ? Wlo : Whi) +
                (size_t)(rowBase + a_row[i]) * GK + k0 + a_kq[i] * 8;
            uint32_t dst = so + (a_hl[i] ? A_LO : A_HI) + a_row[i] * 80 + a_kq[i] * 16;
            CP_ASYNC16(dst, src);
        }
#pragma unroll
        for (int i = 0; i < 4; i++) {
            const __nv_bfloat16* src = (b_hl[i] ? xl : xh) +
                (size_t)(k0 + b_row[i]) * GN + colBase + b_nq[i] * 8;
            uint32_t dst = so + (b_hl[i] ? B_LO : B_HI) + b_row[i] * 272 + b_nq[i] * 16;
            CP_ASYNC16(dst, src);
        }
        CP_COMMIT();
    };

    float acc[4][4][4];
#pragma unroll
    for (int mi = 0; mi < 4; mi++)
#pragma unroll
        for (int ni = 0; ni < 4; ni++)
#pragma unroll
            for (int j = 0; j < 4; j++) acc[mi][ni][j] = 0.f;

    load_stage(0, 0);
    CP_WAIT0();
    __syncthreads();

    const int a_r = lane & 15;           // ldmatrix row within 16
    const int a_c8 = (lane >> 4) * 8;    // k sub-block
    const int b_r = lane & 15;           // k row for trans ldmatrix

    for (int c = 0; c < 32; c++) {
        const int st = c & 1;
        if (c + 1 < 32) load_stage(c + 1, st ^ 1);

        const uint32_t so = sb + st * STG;
#pragma unroll
        for (int kh = 0; kh < 2; kh++) {
            const int kk = kh * 16;
            uint32_t ah[4][4], al[4][4], bh[4][2], bl[4][2];
#pragma unroll
            for (int mi = 0; mi < 4; mi++) {
                uint32_t off = (uint32_t)(wm * 64 + mi * 16 + a_r) * 80 +
                               (kk + a_c8) * 2;
                LDSM_X4(ah[mi][0], ah[mi][1], ah[mi][2], ah[mi][3], so + A_HI + off);
                LDSM_X4(al[mi][0], al[mi][1], al[mi][2], al[mi][3], so + A_LO + off);
            }
#pragma unroll
            for (int ni = 0; ni < 4; ni++) {
                uint32_t off = (uint32_t)(kk + b_r) * 272 + (wn * 32 + ni * 8) * 2;
                LDSM_X2T(bh[ni][0], bh[ni][1], so + B_HI + off);
                LDSM_X2T(bl[ni][0], bl[ni][1], so + B_LO + off);
            }
#pragma unroll
            for (int mi = 0; mi < 4; mi++)
#pragma unroll
                for (int ni = 0; ni < 4; ni++) {
                    MMA_BF16(acc[mi][ni], ah[mi], bh[ni]);
                    MMA_BF16(acc[mi][ni], ah[mi], bl[ni]);
                    MMA_BF16(acc[mi][ni], al[mi], bh[ni]);
                }
        }
        if (c + 1 < 32) CP_WAIT0();
        __syncthreads();
    }

    // Epilogue: thread t of warp holds rows r0=mi*16+t/4, r1=r0+8; cols ni*8+2*(t%4)
    const int tq = lane >> 2, tr = lane & 3;
#pragma unroll
    for (int mi = 0; mi < 4; mi++) {
        const int r0 = rowBase + wm * 64 + mi * 16 + tq;
        const int r1 = r0 + 8;
        const float bv0 = bias[r0];
        const float bv1 = bias[r1];
        float* p0 = Cb + (size_t)r0 * GN + colBase + wn * 32 + tr * 2;
        float* p1 = Cb + (size_t)r1 * GN + colBase + wn * 32 + tr * 2;
#pragma unroll
        for (int ni = 0; ni < 4; ni++) {
            *(float2*)(p0 + ni * 8) = make_float2(acc[mi][ni][0] + bv0,
                                                  acc[mi][ni][1] + bv0);
            *(float2*)(p1 + ni * 8) = make_float2(acc[mi][ni][2] + bv1,
                                                  acc[mi][ni][3] + bv1);
        }
    }
}

// ---------------------------------------------------------------------------
// Depthwise conv3 (pad 1) + bias + L2-normalize over T (q,k channels only).
// ---------------------------------------------------------------------------
__global__ __launch_bounds__(256) void conv_norm_kernel(
    const float* __restrict__ in, const float* __restrict__ w_dw,
    const float* __restrict__ b_dw, float* __restrict__ out)
{
    __shared__ __align__(16) float s[Tlen + 8];
    __shared__ float red[8];

    const int row = blockIdx.x;
    const int ch  = row % C3;
    const float* inr  = in  + (size_t)row * Tlen;
    float*       outr = out + (size_t)row * Tlen;
    const int tid = threadIdx.x;

    if (tid == 0) { s[3] = 0.f; s[4 + Tlen] = 0.f; }
#pragma unroll
    for (int j = 0; j < 4; j++) {
        int t4 = tid + j * 256;
        *(float4*)&s[4 + t4 * 4] = *(const float4*)(inr + t4 * 4);
    }
    __syncthreads();

    const float w0 = w_dw[ch * 3 + 0];
    const float w1 = w_dw[ch * 3 + 1];
    const float w2 = w_dw[ch * 3 + 2];
    const float bb = b_dw[ch];

    float vals[16];
    float ss = 0.f;
#pragma unroll
    for (int j = 0; j < 4; j++) {
        int t = (tid + j * 256) * 4;
#pragma unroll
        for (int i = 0; i < 4; i++) {
            float v = w0 * s[3 + t + i] + w1 * s[4 + t + i] + w2 * s[5 + t + i] + bb;
            vals[j * 4 + i] = v;
            ss += v * v;
        }
    }

    float scale = 1.f;
    if (ch < 2 * Cch) {
#pragma unroll
        for (int o = 16; o > 0; o >>= 1) ss += __shfl_xor_sync(0xffffffffu, ss, o);
        if ((tid & 31) == 0) red[tid >> 5] = ss;
        __syncthreads();
        if (tid < 32) {
            float r = (tid < 8) ? red[tid] : 0.f;
#pragma unroll
            for (int o = 4; o > 0; o >>= 1) r += __shfl_xor_sync(0xffffffffu, r, o);
            if (tid == 0) red[0] = r;
        }
        __syncthreads();
        float n = sqrtf(red[0]);
        scale = 1.f / fmaxf(n, 1e-12f);
    }

#pragma unroll
    for (int j = 0; j < 4; j++) {
        int t = (tid + j * 256) * 4;
        float4 o4 = make_float4(vals[j * 4 + 0] * scale, vals[j * 4 + 1] * scale,
                                vals[j * 4 + 2] * scale, vals[j * 4 + 3] * scale);
        *(float4*)(outr + t) = o4;
    }
}

// ---------------------------------------------------------------------------
// Cross-covariance attention per (b,h): softmax((q @ k^T)*temp) @ v
// ---------------------------------------------------------------------------
__global__ __launch_bounds__(256) void attn_kernel(
    const float* __restrict__ conv, const float* __restrict__ temp,
    float* __restrict__ out)
{
    __shared__ float smA[64][65];
    __shared__ float smB[64][65];

    const int bh = blockIdx.x;
    const int b = bh >> 4, h = bh & 15;
    const float* qp = conv + ((size_t)b * C3 + h * Dd) * Tlen;
    const float* kp = qp + (size_t)Cch * Tlen;
    const float* vp = qp + (size_t)2 * Cch * Tlen;
    float*       op = out + ((size_t)b * Cch + h * Dd) * Tlen;

    const int tid = threadIdx.x;
    const int tx = tid & 15, ty = tid >> 4;

    float acc[4][4];
#pragma unroll
    for (int i = 0; i < 4; i++)
#pragma unroll
        for (int j = 0; j < 4; j++) acc[i][j] = 0.f;

    for (int t0 = 0; t0 < Tlen; t0 += 64) {
        for (int i = tid; i < 64 * 16; i += 256) {
            int r = i >> 4;
            int c = (i & 15) << 2;
            float4 qv = *(const float4*)(qp + (size_t)r * Tlen + t0 + c);
            float4 kv = *(const float4*)(kp + (size_t)r * Tlen + t0 + c);
            smA[r][c] = qv.x; smA[r][c + 1] = qv.y; smA[r][c + 2] = qv.z; smA[r][c + 3] = qv.w;
            smB[r][c] = kv.x; smB[r][c + 1] = kv.y; smB[r][c + 2] = kv.z; smB[r][c + 3] = kv.w;
        }
        __syncthreads();
#pragma unroll 16
        for (int kk = 0; kk < 64; kk++) {
            float a[4], bv[4];
#pragma unroll
            for (int i = 0; i < 4; i++) a[i]  = smA[ty * 4 + i][kk];
#pragma unroll
            for (int j = 0; j < 4; j++) bv[j] = smB[tx * 4 + j][kk];
#pragma unroll
            for (int i = 0; i < 4; i++)
#pragma unroll
                for (int j = 0; j < 4; j++)
                    acc[i][j] += a[i] * bv[j];
        }
        __syncthreads();
    }

    const float tsc = temp[h];
#pragma unroll
    for (int i = 0; i < 4; i++)
#pragma unroll
        for (int j = 0; j < 4; j++)
            smA[ty * 4 + i][tx * 4 + j] = acc[i][j] * tsc;
    __syncthreads();

    if (tid < 64) {
        float m = -1e30f;
#pragma unroll 8
        for (int e = 0; e < 64; e++) m = fmaxf(m, smA[tid][e]);
        float ssum = 0.f;
#pragma unroll 8
        for (int e = 0; e < 64; e++) {
            float ex = __expf(smA[tid][e] - m);
            smA[tid][e] = ex;
            ssum += ex;
        }
        float inv = 1.f / ssum;
#pragma unroll 8
        for (int e = 0; e < 64; e++) smA[tid][e] *= inv;
    }
    __syncthreads();

    for (int t0 = 0; t0 < Tlen; t0 += 64) {
        for (int i = tid; i < 64 * 16; i += 256) {
            int r = i >> 4;
            int c = (i & 15) << 2;
            float4 vv = *(const float4*)(vp + (size_t)r * Tlen + t0 + c);
            smB[r][c] = vv.x; smB[r][c + 1] = vv.y; smB[r][c + 2] = vv.z; smB[r][c + 3] = vv.w;
        }
        __syncthreads();

        float o4[4][4];
#pragma unroll
        for (int i = 0; i < 4; i++)
#pragma unroll
            for (int j = 0; j < 4; j++) o4[i][j] = 0.f;

#pragma unroll 16
        for (int e = 0; e < 64; e++) {
            float a[4], bv[4];
#pragma unroll
            for (int i = 0; i < 4; i++) a[i]  = smA[ty * 4 + i][e];
#pragma unroll
            for (int j = 0; j < 4; j++) bv[j] = smB[e][tx * 4 + j];
#pragma unroll
            for (int i = 0; i < 4; i++)
#pragma unroll
                for (int j = 0; j < 4; j++)
                    o4[i][j] += a[i] * bv[j];
        }
#pragma unroll
        for (int i = 0; i < 4; i++) {
            float4 w4 = make_float4(o4[i][0], o4[i][1], o4[i][2], o4[i][3]);
            *(float4*)(op + (size_t)(ty * 4 + i) * Tlen + t0 + tx * 4) = w4;
        }
        __syncthreads();
    }
}

// ---------------------------------------------------------------------------
extern "C" void kernel_launch(void* const* d_in, const int* in_sizes, int n_in,
                              void* d_out, int out_size)
{
    (void)in_sizes; (void)n_in; (void)out_size;
    const float* x     = (const float*)d_in[0];
    const float* w_qkv = (const float*)d_in[1];
    const float* b_qkv = (const float*)d_in[2];
    const float* w_dw  = (const float*)d_in[3];
    const float* b_dw  = (const float*)d_in[4];
    const float* w_out = (const float*)d_in[5];
    const float* b_out = (const float*)d_in[6];
    const float* temp  = (const float*)d_in[7];
    float* out = (float*)d_out;

    float *qkv_buf, *conv_buf;
    __nv_bfloat16 *xhi, *xlo, *whi, *wlo;
    cudaGetSymbolAddress((void**)&qkv_buf,  g_qkv);
    cudaGetSymbolAddress((void**)&conv_buf, g_conv);
    cudaGetSymbolAddress((void**)&xhi, g_xhi);
    cudaGetSymbolAddress((void**)&xlo, g_xlo);
    cudaGetSymbolAddress((void**)&whi, g_whi);
    cudaGetSymbolAddress((void**)&wlo, g_wlo);

    cudaFuncSetAttribute(gemm_mma_bf16x3,
                         cudaFuncAttributeMaxDynamicSharedMemorySize, GSMEM);

    const size_t wOutOff = (size_t)C3 * Cch;

    // 1) converts: x, w_qkv, w_out -> bf16 hi/lo
    cvt_hilo<<<(Bsz * Cch * Tlen / 4) / 256, 256>>>(x, xhi, xlo, Bsz * Cch * Tlen / 4);
    cvt_hilo<<<(C3 * Cch / 4) / 256, 256>>>(w_qkv, whi, wlo, C3 * Cch / 4);
    cvt_hilo<<<(Cch * Cch / 4) / 256, 256>>>(w_out, whi + wOutOff, wlo + wOutOff,
                                             Cch * Cch / 4);

    // 2) QKV GEMM (tensor cores): [3072,1024] @ [1024,4096] + b_qkv
    {
        dim3 grid(Tlen / 128, C3 / 128, Bsz);
        gemm_mma_bf16x3<<<grid, 256, GSMEM>>>(whi, wlo, xhi, xlo, b_qkv, qkv_buf,
                                              (size_t)C3 * Tlen);
    }
    // 3) depthwise conv3 + bias + L2 norm
    conv_norm_kernel<<<Bsz * C3, 256>>>(qkv_buf, w_dw, b_dw, conv_buf);

    // 4) attention (writes [B,1024,T] into g_qkv)
    attn_kernel<<<Bsz * Hh, 256>>>(conv_buf, temp, qkv_buf);

    // 5) convert attention output -> bf16 hi/lo (reuse xhi/xlo)
    cvt_hilo<<<(Bsz * Cch * Tlen / 4) / 256, 256>>>(qkv_buf, xhi, xlo,
                                                    Bsz * Cch * Tlen / 4);

    // 6) output projection GEMM: [1024,1024] @ [1024,4096] + b_out
    {
        dim3 grid(Tlen / 128, Cch / 128, Bsz);
        gemm_mma_bf16x3<<<grid, 256, GSMEM>>>(whi + wOutOff, wlo + wOutOff, xhi, xlo,
                                              b_out, out, (size_t)Cch * Tlen);
    }
}

// round 6
// speedup vs baseline: 2.6644x; 1.2096x over previous
#include <cuda_runtime.h>
#include <cuda_bf16.h>
#include <math.h>
#include <stdint.h>

#define Bsz  8
#define Cch  1024
#define Tlen 4096
#define Hh   16
#define Dd   64
#define C3   3072

// ---------------------------------------------------------------------------
// Scratch (allocation-free __device__ globals)
// ---------------------------------------------------------------------------
__device__ float g_qkv[(size_t)Bsz * C3 * Tlen];               // qkv out; later: logit scratch
__device__ float g_conv[(size_t)Bsz * C3 * Tlen];              // conv+norm out
__device__ __nv_bfloat16 g_xhi[(size_t)Bsz * Cch * Tlen];      // activation hi
__device__ __nv_bfloat16 g_xlo[(size_t)Bsz * Cch * Tlen];      // activation lo
__device__ __nv_bfloat16 g_whi[(size_t)(C3 + Cch) * Cch];      // weights hi (qkv|out)
__device__ __nv_bfloat16 g_wlo[(size_t)(C3 + Cch) * Cch];      // weights lo

#define NCHUNK 8
#define TCH    (Tlen / NCHUNK)   // 512

// ---------------------------------------------------------------------------
// PTX helpers (sm_80+ portable: cp.async, ldmatrix, mma.sync bf16)
// ---------------------------------------------------------------------------
__device__ __forceinline__ uint32_t s2u(const void* p) {
    uint32_t a;
    asm("{ .reg .u64 t; cvta.to.shared.u64 t, %1; cvt.u32.u64 %0, t; }"
        : "=r"(a) : "l"(p));
    return a;
}

#define CP_ASYNC16(dst, src) \
    asm volatile("cp.async.ca.shared.global [%0], [%1], 16;" \
                 :: "r"(dst), "l"(src) : "memory")
#define CP_COMMIT() asm volatile("cp.async.commit_group;" ::: "memory")
#define CP_WAIT1()  asm volatile("cp.async.wait_group 1;"  ::: "memory")

#define LDSM_X4(r0, r1, r2, r3, addr) \
    asm volatile("ldmatrix.sync.aligned.m8n8.x4.shared.b16 {%0,%1,%2,%3}, [%4];" \
                 : "=r"(r0), "=r"(r1), "=r"(r2), "=r"(r3) : "r"(addr))
#define LDSM_X2T(r0, r1, addr) \
    asm volatile("ldmatrix.sync.aligned.m8n8.x2.trans.shared.b16 {%0,%1}, [%2];" \
                 : "=r"(r0), "=r"(r1) : "r"(addr))

#define MMA_BF16(d, a, b) \
    asm volatile("mma.sync.aligned.m16n8k16.row.col.f32.bf16.bf16.f32 " \
                 "{%0,%1,%2,%3}, {%4,%5,%6,%7}, {%8,%9}, {%0,%1,%2,%3};" \
                 : "+f"((d)[0]), "+f"((d)[1]), "+f"((d)[2]), "+f"((d)[3]) \
                 : "r"((a)[0]), "r"((a)[1]), "r"((a)[2]), "r"((a)[3]), \
                   "r"((b)[0]), "r"((b)[1]))

// ---------------------------------------------------------------------------
// fp32 -> bf16 hi/lo split conversion
// ---------------------------------------------------------------------------
__global__ __launch_bounds__(256) void cvt_hilo(
    const float* __restrict__ in, __nv_bfloat16* __restrict__ hi,
    __nv_bfloat16* __restrict__ lo, int n4)
{
    int i = blockIdx.x * blockDim.x + threadIdx.x;
    if (i >= n4) return;
    float4 v = ((const float4*)in)[i];
    __nv_bfloat16 h0 = __float2bfloat16(v.x);
    __nv_bfloat16 h1 = __float2bfloat16(v.y);
    __nv_bfloat16 h2 = __float2bfloat16(v.z);
    __nv_bfloat16 h3 = __float2bfloat16(v.w);
    __nv_bfloat16 l0 = __float2bfloat16(v.x - __bfloat162float(h0));
    __nv_bfloat16 l1 = __float2bfloat16(v.y - __bfloat162float(h1));
    __nv_bfloat16 l2 = __float2bfloat16(v.z - __bfloat162float(h2));
    __nv_bfloat16 l3 = __float2bfloat16(v.w - __bfloat162float(h3));
    __nv_bfloat162* hp = (__nv_bfloat162*)hi;
    __nv_bfloat162* lp = (__nv_bfloat162*)lo;
    hp[2 * i]     = __nv_bfloat162(h0, h1);
    hp[2 * i + 1] = __nv_bfloat162(h2, h3);
    lp[2 * i]     = __nv_bfloat162(l0, l1);
    lp[2 * i + 1] = __nv_bfloat162(l2, l3);
}

// ---------------------------------------------------------------------------
// bf16x3 GEMM via mma.sync: C[b] = W[M,1024] @ X[b][1024,4096] + bias
// CTA: 128x128, BK=32, 256 threads (8 warps, 64x32 each). 3-stage cp.async.
// ---------------------------------------------------------------------------
#define GK   1024
#define GN   4096
#define A_HI 0
#define A_LO 10240
#define B_HI 20480
#define B_LO 29184
#define STG  37888
#define NSTAGE 3
#define GSMEM (NSTAGE * STG)

__global__ __launch_bounds__(256) void gemm_mma_bf16x3(
    const __nv_bfloat16* __restrict__ Whi, const __nv_bfloat16* __restrict__ Wlo,
    const __nv_bfloat16* __restrict__ Xhi, const __nv_bfloat16* __restrict__ Xlo,
    const float* __restrict__ bias, float* __restrict__ C, size_t strideC)
{
    extern __shared__ char smem[];
    const uint32_t sb = s2u(smem);
    const int tid  = threadIdx.x;
    const int wid  = tid >> 5;
    const int lane = tid & 31;
    const int wm = wid & 1;
    const int wn = wid >> 1;
    const int rowBase = blockIdx.y * 128;
    const int colBase = blockIdx.x * 128;
    const size_t bOff = (size_t)blockIdx.z * GK * GN;
    const __nv_bfloat16* xh = Xhi + bOff;
    const __nv_bfloat16* xl = Xlo + bOff;
    float* Cb = C + (size_t)blockIdx.z * strideC;

    int a_hl[4], a_row[4], a_kq[4], b_hl[4], b_row[4], b_nq[4];
#pragma unroll
    for (int i = 0; i < 4; i++) {
        int u = tid + i * 256;
        a_hl[i] = u >> 9;  int v = u & 511;
        a_row[i] = v >> 2; a_kq[i] = v & 3;
        b_hl[i] = u >> 9;
        b_row[i] = v >> 4; b_nq[i] = v & 15;
    }

    auto load_stage = [&](int c, int st) {
        const uint32_t so = sb + st * STG;
        const int k0 = c * 32;
#pragma unroll
        for (int i = 0; i < 4; i++) {
            const __nv_bfloat16* src = (a_hl[i] ? Wlo : Whi) +
                (size_t)(rowBase + a_row[i]) * GK + k0 + a_kq[i] * 8;
            uint32_t dst = so + (a_hl[i] ? A_LO : A_HI) + a_row[i] * 80 + a_kq[i] * 16;
            CP_ASYNC16(dst, src);
        }
#pragma unroll
        for (int i = 0; i < 4; i++) {
            const __nv_bfloat16* src = (b_hl[i] ? xl : xh) +
                (size_t)(k0 + b_row[i]) * GN + colBase + b_nq[i] * 8;
            uint32_t dst = so + (b_hl[i] ? B_LO : B_HI) + b_row[i] * 272 + b_nq[i] * 16;
            CP_ASYNC16(dst, src);
        }
        CP_COMMIT();
    };

    float acc[4][4][4];
#pragma unroll
    for (int mi = 0; mi < 4; mi++)
#pragma unroll
        for (int ni = 0; ni < 4; ni++)
#pragma unroll
            for (int j = 0; j < 4; j++) acc[mi][ni][j] = 0.f;

    load_stage(0, 0);
    load_stage(1, 1);

    const int a_r = lane & 15;
    const int a_c8 = (lane >> 4) * 8;
    const int b_r = lane & 15;

    int st = 0;
    for (int c = 0; c < 32; c++) {
        CP_WAIT1();            // stage c resident (loaded 2 iters ago)
        __syncthreads();

        const uint32_t so = sb + st * STG;
#pragma unroll
        for (int kh = 0; kh < 2; kh++) {
            const int kk = kh * 16;
            uint32_t ah[4][4], al[4][4], bh[4][2], bl[4][2];
#pragma unroll
            for (int mi = 0; mi < 4; mi++) {
                uint32_t off = (uint32_t)(wm * 64 + mi * 16 + a_r) * 80 +
                               (kk + a_c8) * 2;
                LDSM_X4(ah[mi][0], ah[mi][1], ah[mi][2], ah[mi][3], so + A_HI + off);
                LDSM_X4(al[mi][0], al[mi][1], al[mi][2], al[mi][3], so + A_LO + off);
            }
#pragma unroll
            for (int ni = 0; ni < 4; ni++) {
                uint32_t off = (uint32_t)(kk + b_r) * 272 + (wn * 32 + ni * 8) * 2;
                LDSM_X2T(bh[ni][0], bh[ni][1], so + B_HI + off);
                LDSM_X2T(bl[ni][0], bl[ni][1], so + B_LO + off);
            }
#pragma unroll
            for (int mi = 0; mi < 4; mi++)
#pragma unroll
                for (int ni = 0; ni < 4; ni++) {
                    MMA_BF16(acc[mi][ni], ah[mi], bh[ni]);
                    MMA_BF16(acc[mi][ni], ah[mi], bl[ni]);
                    MMA_BF16(acc[mi][ni], al[mi], bh[ni]);
                }
        }
        if (c + 2 < 32) load_stage(c + 2, (st + 2 >= NSTAGE) ? st + 2 - NSTAGE : st + 2);
        st = (st + 1 >= NSTAGE) ? 0 : st + 1;
    }

    const int tq = lane >> 2, tr = lane & 3;
#pragma unroll
    for (int mi = 0; mi < 4; mi++) {
        const int r0 = rowBase + wm * 64 + mi * 16 + tq;
        const int r1 = r0 + 8;
        const float bv0 = bias[r0];
        const float bv1 = bias[r1];
        float* p0 = Cb + (size_t)r0 * GN + colBase + wn * 32 + tr * 2;
        float* p1 = Cb + (size_t)r1 * GN + colBase + wn * 32 + tr * 2;
#pragma unroll
        for (int ni = 0; ni < 4; ni++) {
            *(float2*)(p0 + ni * 8) = make_float2(acc[mi][ni][0] + bv0,
                                                  acc[mi][ni][1] + bv0);
            *(float2*)(p1 + ni * 8) = make_float2(acc[mi][ni][2] + bv1,
                                                  acc[mi][ni][3] + bv1);
        }
    }
}

// ---------------------------------------------------------------------------
// Depthwise conv3 (pad 1) + bias + L2-normalize over T (q,k channels only).
// ---------------------------------------------------------------------------
__global__ __launch_bounds__(256) void conv_norm_kernel(
    const float* __restrict__ in, const float* __restrict__ w_dw,
    const float* __restrict__ b_dw, float* __restrict__ out)
{
    __shared__ __align__(16) float s[Tlen + 8];
    __shared__ float red[8];

    const int row = blockIdx.x;
    const int ch  = row % C3;
    const float* inr  = in  + (size_t)row * Tlen;
    float*       outr = out + (size_t)row * Tlen;
    const int tid = threadIdx.x;

    if (tid == 0) { s[3] = 0.f; s[4 + Tlen] = 0.f; }
#pragma unroll
    for (int j = 0; j < 4; j++) {
        int t4 = tid + j * 256;
        *(float4*)&s[4 + t4 * 4] = *(const float4*)(inr + t4 * 4);
    }
    __syncthreads();

    const float w0 = w_dw[ch * 3 + 0];
    const float w1 = w_dw[ch * 3 + 1];
    const float w2 = w_dw[ch * 3 + 2];
    const float bb = b_dw[ch];

    float vals[16];
    float ss = 0.f;
#pragma unroll
    for (int j = 0; j < 4; j++) {
        int t = (tid + j * 256) * 4;
#pragma unroll
        for (int i = 0; i < 4; i++) {
            float v = w0 * s[3 + t + i] + w1 * s[4 + t + i] + w2 * s[5 + t + i] + bb;
            vals[j * 4 + i] = v;
            ss += v * v;
        }
    }

    float scale = 1.f;
    if (ch < 2 * Cch) {
#pragma unroll
        for (int o = 16; o > 0; o >>= 1) ss += __shfl_xor_sync(0xffffffffu, ss, o);
        if ((tid & 31) == 0) red[tid >> 5] = ss;
        __syncthreads();
        if (tid < 32) {
            float r = (tid < 8) ? red[tid] : 0.f;
#pragma unroll
            for (int o = 4; o > 0; o >>= 1) r += __shfl_xor_sync(0xffffffffu, r, o);
            if (tid == 0) red[0] = r;
        }
        __syncthreads();
        float n = sqrtf(red[0]);
        scale = 1.f / fmaxf(n, 1e-12f);
    }

#pragma unroll
    for (int j = 0; j < 4; j++) {
        int t = (tid + j * 256) * 4;
        float4 o4 = make_float4(vals[j * 4 + 0] * scale, vals[j * 4 + 1] * scale,
                                vals[j * 4 + 2] * scale, vals[j * 4 + 3] * scale);
        *(float4*)(outr + t) = o4;
    }
}

// ---------------------------------------------------------------------------
// attn_qk: partial logits over a T-chunk. grid (NCHUNK, B*H).
// part[(bh*NCHUNK + chunk)][64][64]
// ---------------------------------------------------------------------------
__global__ __launch_bounds__(256) void attn_qk(
    const float* __restrict__ conv, float* __restrict__ part)
{
    __shared__ float smA[64][65];
    __shared__ float smB[64][65];

    const int chunk = blockIdx.x;
    const int bh = blockIdx.y;
    const int b = bh >> 4, h = bh & 15;
    const float* qp = conv + ((size_t)b * C3 + h * Dd) * Tlen;
    const float* kp = qp + (size_t)Cch * Tlen;

    const int tid = threadIdx.x;
    const int tx = tid & 15, ty = tid >> 4;

    float acc[4][4];
#pragma unroll
    for (int i = 0; i < 4; i++)
#pragma unroll
        for (int j = 0; j < 4; j++) acc[i][j] = 0.f;

    for (int t0 = chunk * TCH; t0 < (chunk + 1) * TCH; t0 += 64) {
        for (int i = tid; i < 64 * 16; i += 256) {
            int r = i >> 4;
            int c = (i & 15) << 2;
            float4 qv = *(const float4*)(qp + (size_t)r * Tlen + t0 + c);
            float4 kv = *(const float4*)(kp + (size_t)r * Tlen + t0 + c);
            smA[r][c] = qv.x; smA[r][c + 1] = qv.y; smA[r][c + 2] = qv.z; smA[r][c + 3] = qv.w;
            smB[r][c] = kv.x; smB[r][c + 1] = kv.y; smB[r][c + 2] = kv.z; smB[r][c + 3] = kv.w;
        }
        __syncthreads();
#pragma unroll 16
        for (int kk = 0; kk < 64; kk++) {
            float a[4], bv[4];
#pragma unroll
            for (int i = 0; i < 4; i++) a[i]  = smA[ty * 4 + i][kk];
#pragma unroll
            for (int j = 0; j < 4; j++) bv[j] = smB[tx * 4 + j][kk];
#pragma unroll
            for (int i = 0; i < 4; i++)
#pragma unroll
                for (int j = 0; j < 4; j++)
                    acc[i][j] += a[i] * bv[j];
        }
        __syncthreads();
    }

    float* pp = part + ((size_t)bh * NCHUNK + chunk) * 4096;
#pragma unroll
    for (int i = 0; i < 4; i++)
#pragma unroll
        for (int j = 0; j < 4; j++)
            pp[(ty * 4 + i) * 64 + tx * 4 + j] = acc[i][j];
}

// ---------------------------------------------------------------------------
// attn_soft: sum partials, *temp, softmax rows -> attnm[bh][64][64]
// ---------------------------------------------------------------------------
__global__ __launch_bounds__(256) void attn_soft(
    const float* __restrict__ part, const float* __restrict__ temp,
    float* __restrict__ attnm)
{
    __shared__ float sm[64][64];
    const int bh = blockIdx.x;
    const int h = bh & 15;
    const int tid = threadIdx.x;
    const float tsc = temp[h];
    const float* pp = part + (size_t)bh * NCHUNK * 4096;

    for (int i = tid; i < 4096; i += 256) {
        float s = 0.f;
#pragma unroll
        for (int c = 0; c < NCHUNK; c++) s += pp[c * 4096 + i];
        sm[i >> 6][i & 63] = s * tsc;
    }
    __syncthreads();

    const int wid = tid >> 5, lane = tid & 31;
    float* am = attnm + (size_t)bh * 4096;
#pragma unroll
    for (int rr = 0; rr < 8; rr++) {
        const int r = wid * 8 + rr;
        float v0 = sm[r][lane], v1 = sm[r][lane + 32];
        float m = fmaxf(v0, v1);
#pragma unroll
        for (int o = 16; o > 0; o >>= 1) m = fmaxf(m, __shfl_xor_sync(0xffffffffu, m, o));
        float e0 = __expf(v0 - m), e1 = __expf(v1 - m);
        float s = e0 + e1;
#pragma unroll
        for (int o = 16; o > 0; o >>= 1) s += __shfl_xor_sync(0xffffffffu, s, o);
        float inv = 1.f / s;
        am[r * 64 + lane]      = e0 * inv;
        am[r * 64 + lane + 32] = e1 * inv;
    }
}

// ---------------------------------------------------------------------------
// attn_v: out[:, chunk] = A @ v[:, chunk], write bf16 hi/lo directly.
// grid (NCHUNK, B*H)
// ---------------------------------------------------------------------------
__global__ __launch_bounds__(256) void attn_v(
    const float* __restrict__ conv, const float* __restrict__ attnm,
    __nv_bfloat16* __restrict__ ohi, __nv_bfloat16* __restrict__ olo)
{
    __shared__ float smA[64][65];
    __shared__ float smB[64][65];

    const int chunk = blockIdx.x;
    const int bh = blockIdx.y;
    const int b = bh >> 4, h = bh & 15;
    const float* vp = conv + ((size_t)b * C3 + 2 * Cch + h * Dd) * Tlen;
    const size_t oBase = ((size_t)b * Cch + h * Dd) * Tlen;

    const int tid = threadIdx.x;
    const int tx = tid & 15, ty = tid >> 4;

    const float* am = attnm + (size_t)bh * 4096;
    for (int i = tid; i < 4096; i += 256)
        smA[i >> 6][i & 63] = am[i];
    __syncthreads();

    for (int t0 = chunk * TCH; t0 < (chunk + 1) * TCH; t0 += 64) {
        for (int i = tid; i < 64 * 16; i += 256) {
            int r = i >> 4;
            int c = (i & 15) << 2;
            float4 vv = *(const float4*)(vp + (size_t)r * Tlen + t0 + c);
            smB[r][c] = vv.x; smB[r][c + 1] = vv.y; smB[r][c + 2] = vv.z; smB[r][c + 3] = vv.w;
        }
        __syncthreads();

        float o4[4][4];
#pragma unroll
        for (int i = 0; i < 4; i++)
#pragma unroll
            for (int j = 0; j < 4; j++) o4[i][j] = 0.f;

#pragma unroll 16
        for (int e = 0; e < 64; e++) {
            float a[4], bv[4];
#pragma unroll
            for (int i = 0; i < 4; i++) a[i]  = smA[ty * 4 + i][e];
#pragma unroll
            for (int j = 0; j < 4; j++) bv[j] = smB[e][tx * 4 + j];
#pragma unroll
            for (int i = 0; i < 4; i++)
#pragma unroll
                for (int j = 0; j < 4; j++)
                    o4[i][j] += a[i] * bv[j];
        }
#pragma unroll
        for (int i = 0; i < 4; i++) {
            size_t off = oBase + (size_t)(ty * 4 + i) * Tlen + t0 + tx * 4;
            __nv_bfloat16 hv[4], lv[4];
#pragma unroll
            for (int j = 0; j < 4; j++) {
                hv[j] = __float2bfloat16(o4[i][j]);
                lv[j] = __float2bfloat16(o4[i][j] - __bfloat162float(hv[j]));
            }
            *(uint2*)(ohi + off) = *(uint2*)hv;
            *(uint2*)(olo + off) = *(uint2*)lv;
        }
        __syncthreads();
    }
}

// ---------------------------------------------------------------------------
extern "C" void kernel_launch(void* const* d_in, const int* in_sizes, int n_in,
                              void* d_out, int out_size)
{
    (void)in_sizes; (void)n_in; (void)out_size;
    const float* x     = (const float*)d_in[0];
    const float* w_qkv = (const float*)d_in[1];
    const float* b_qkv = (const float*)d_in[2];
    const float* w_dw  = (const float*)d_in[3];
    const float* b_dw  = (const float*)d_in[4];
    const float* w_out = (const float*)d_in[5];
    const float* b_out = (const float*)d_in[6];
    const float* temp  = (const float*)d_in[7];
    float* out = (float*)d_out;

    float *qkv_buf, *conv_buf;
    __nv_bfloat16 *xhi, *xlo, *whi, *wlo;
    cudaGetSymbolAddress((void**)&qkv_buf,  g_qkv);
    cudaGetSymbolAddress((void**)&conv_buf, g_conv);
    cudaGetSymbolAddress((void**)&xhi, g_xhi);
    cudaGetSymbolAddress((void**)&xlo, g_xlo);
    cudaGetSymbolAddress((void**)&whi, g_whi);
    cudaGetSymbolAddress((void**)&wlo, g_wlo);

    cudaFuncSetAttribute(gemm_mma_bf16x3,
                         cudaFuncAttributeMaxDynamicSharedMemorySize, GSMEM);

    const size_t wOutOff = (size_t)C3 * Cch;
    // scratch inside g_qkv once it is free (after conv_norm)
    float* part  = qkv_buf;                               // 128*8*4096 floats
    float* attnm = qkv_buf + (size_t)128 * NCHUNK * 4096; // 128*4096 floats

    // 1) converts
    cvt_hilo<<<(Bsz * Cch * Tlen / 4) / 256, 256>>>(x, xhi, xlo, Bsz * Cch * Tlen / 4);
    cvt_hilo<<<(C3 * Cch / 4) / 256, 256>>>(w_qkv, whi, wlo, C3 * Cch / 4);
    cvt_hilo<<<(Cch * Cch / 4) / 256, 256>>>(w_out, whi + wOutOff, wlo + wOutOff,
                                             Cch * Cch / 4);

    // 2) QKV GEMM
    {
        dim3 grid(Tlen / 128, C3 / 128, Bsz);
        gemm_mma_bf16x3<<<grid, 256, GSMEM>>>(whi, wlo, xhi, xlo, b_qkv, qkv_buf,
                                              (size_t)C3 * Tlen);
    }
    // 3) depthwise conv3 + bias + L2 norm
    conv_norm_kernel<<<Bsz * C3, 256>>>(qkv_buf, w_dw, b_dw, conv_buf);

    // 4) attention, chunked (g_qkv reused as logit scratch)
    attn_qk<<<dim3(NCHUNK, Bsz * Hh), 256>>>(conv_buf, part);
    attn_soft<<<Bsz * Hh, 256>>>(part, temp, attnm);
    attn_v<<<dim3(NCHUNK, Bsz * Hh), 256>>>(conv_buf, attnm, xhi, xlo);

    // 5) output projection GEMM
    {
        dim3 grid(Tlen / 128, Cch / 128, Bsz);
        gemm_mma_bf16x3<<<grid, 256, GSMEM>>>(whi + wOutOff, wlo + wOutOff, xhi, xlo,
                                              b_out, out, (size_t)Cch * Tlen);
    }
}

// round 9
// speedup vs baseline: 3.4087x; 1.2794x over previous
#include <cuda_runtime.h>
#include <cuda_fp16.h>
#include <math.h>
#include <stdint.h>

#define Bsz  8
#define Cch  1024
#define Tlen 4096
#define Hh   16
#define Dd   64
#define C3   3072

// ---------------------------------------------------------------------------
// Scratch (allocation-free __device__ globals)
// ---------------------------------------------------------------------------
__device__ float g_qkv[(size_t)Bsz * C3 * Tlen];          // qkv out; later logit scratch
__device__ float g_conv[(size_t)Bsz * C3 * Tlen];         // conv+norm out
__device__ __half g_xf16[(size_t)Bsz * Cch * Tlen];       // activations fp16 (x / attn out)
__device__ __half g_whi[(size_t)(C3 + Cch) * Cch];        // weights hi (qkv|out)
__device__ __half g_wlo[(size_t)(C3 + Cch) * Cch];        // weights lo

#define NCHUNK 8
#define TCH    (Tlen / NCHUNK)   // 512

// ---------------------------------------------------------------------------
// PTX helpers (sm_80+ portable)
// ---------------------------------------------------------------------------
__device__ __forceinline__ uint32_t s2u(const void* p) {
    uint32_t a;
    asm("{ .reg .u64 t; cvta.to.shared.u64 t, %1; cvt.u32.u64 %0, t; }"
        : "=r"(a) : "l"(p));
    return a;
}

#define CP_ASYNC16(dst, src) \
    asm volatile("cp.async.ca.shared.global [%0], [%1], 16;" \
                 :: "r"(dst), "l"(src) : "memory")
#define CP_COMMIT() asm volatile("cp.async.commit_group;" ::: "memory")
#define CP_WAIT1()  asm volatile("cp.async.wait_group 1;"  ::: "memory")

#define LDSM_X4(r0, r1, r2, r3, addr) \
    asm volatile("ldmatrix.sync.aligned.m8n8.x4.shared.b16 {%0,%1,%2,%3}, [%4];" \
                 : "=r"(r0), "=r"(r1), "=r"(r2), "=r"(r3) : "r"(addr))
#define LDSM_X2T(r0, r1, addr) \
    asm volatile("ldmatrix.sync.aligned.m8n8.x2.trans.shared.b16 {%0,%1}, [%2];" \
                 : "=r"(r0), "=r"(r1) : "r"(addr))

#define MMA_F16(d, a, b) \
    asm volatile("mma.sync.aligned.m16n8k16.row.col.f32.f16.f16.f32 " \
                 "{%0,%1,%2,%3}, {%4,%5,%6,%7}, {%8,%9}, {%0,%1,%2,%3};" \
                 : "+f"((d)[0]), "+f"((d)[1]), "+f"((d)[2]), "+f"((d)[3]) \
                 : "r"((a)[0]), "r"((a)[1]), "r"((a)[2]), "r"((a)[3]), \
                   "r"((b)[0]), "r"((b)[1]))

// ---------------------------------------------------------------------------
// Converts
// ---------------------------------------------------------------------------
__global__ __launch_bounds__(256) void cvt_w_hilo(
    const float* __restrict__ in, __half* __restrict__ hi,
    __half* __restrict__ lo, int n4)
{
    int i = blockIdx.x * blockDim.x + threadIdx.x;
    if (i >= n4) return;
    float4 v = ((const float4*)in)[i];
    __half h0 = __float2half(v.x), h1 = __float2half(v.y);
    __half h2 = __float2half(v.z), h3 = __float2half(v.w);
    __half l0 = __float2half(v.x - __half2float(h0));
    __half l1 = __float2half(v.y - __half2float(h1));
    __half l2 = __float2half(v.z - __half2float(h2));
    __half l3 = __float2half(v.w - __half2float(h3));
    __half2* hp = (__half2*)hi;
    __half2* lp = (__half2*)lo;
    hp[2 * i]     = __halves2half2(h0, h1);
    hp[2 * i + 1] = __halves2half2(h2, h3);
    lp[2 * i]     = __halves2half2(l0, l1);
    lp[2 * i + 1] = __halves2half2(l2, l3);
}

__global__ __launch_bounds__(256) void cvt_x_f16(
    const float* __restrict__ in, __half* __restrict__ o, int n4)
{
    int i = blockIdx.x * blockDim.x + threadIdx.x;
    if (i >= n4) return;
    float4 v = ((const float4*)in)[i];
    __half2* op = (__half2*)o;
    op[2 * i]     = __halves2half2(__float2half(v.x), __float2half(v.y));
    op[2 * i + 1] = __halves2half2(__float2half(v.z), __float2half(v.w));
}

// ---------------------------------------------------------------------------
// fp16x2 GEMM via mma.sync: C[b] = W[M,1024] @ X[b][1024,4096] + bias
// W split hi/lo fp16, X single fp16. CTA 128x128, BK=32, 256 thr, 3-stage.
// smem/stage: A_hi[128][40] + A_lo[128][40] + B[32][136] halfs = 29184 B
// ---------------------------------------------------------------------------
#define GK   1024
#define GN   4096
#define A_HI 0
#define A_LO 10240
#define B_OF 20480
#define STG  29184
#define NSTAGE 3
#define GSMEM (NSTAGE * STG)

__global__ __launch_bounds__(256) void gemm_mma_f16x2(
    const __half* __restrict__ Whi, const __half* __restrict__ Wlo,
    const __half* __restrict__ X,
    const float* __restrict__ bias, float* __restrict__ C, size_t strideC)
{
    extern __shared__ char smem[];
    const uint32_t sb = s2u(smem);
    const int tid  = threadIdx.x;
    const int wid  = tid >> 5;
    const int lane = tid & 31;
    const int wm = wid & 1;
    const int wn = wid >> 1;
    const int rowBase = blockIdx.y * 128;
    const int colBase = blockIdx.x * 128;
    const __half* Xb = X + (size_t)blockIdx.z * GK * GN;
    float* Cb = C + (size_t)blockIdx.z * strideC;

    // per-thread load coords: 4 A-chunks (of 1024) + 2 B-chunks (of 512)
    int a_hl[4], a_row[4], a_kq[4], b_row[2], b_nq[2];
#pragma unroll
    for (int i = 0; i < 4; i++) {
        int u = tid + i * 256;
        a_hl[i] = u >> 9;  int v = u & 511;
        a_row[i] = v >> 2; a_kq[i] = v & 3;
    }
#pragma unroll
    for (int i = 0; i < 2; i++) {
        int u = tid + i * 256;
        b_row[i] = u >> 4; b_nq[i] = u & 15;
    }

    auto load_stage = [&](int c, int st) {
        const uint32_t so = sb + st * STG;
        const int k0 = c * 32;
#pragma unroll
        for (int i = 0; i < 4; i++) {
            const __half* src = (a_hl[i] ? Wlo : Whi) +
                (size_t)(rowBase + a_row[i]) * GK + k0 + a_kq[i] * 8;
            uint32_t dst = so + (a_hl[i] ? A_LO : A_HI) + a_row[i] * 80 + a_kq[i] * 16;
            CP_ASYNC16(dst, src);
        }
#pragma unroll
        for (int i = 0; i < 2; i++) {
            const __half* src = Xb + (size_t)(k0 + b_row[i]) * GN + colBase + b_nq[i] * 8;
            uint32_t dst = so + B_OF + b_row[i] * 272 + b_nq[i] * 16;
            CP_ASYNC16(dst, src);
        }
        CP_COMMIT();
    };

    float acc[4][4][4];
#pragma unroll
    for (int mi = 0; mi < 4; mi++)
#pragma unroll
        for (int ni = 0; ni < 4; ni++)
#pragma unroll
            for (int j = 0; j < 4; j++) acc[mi][ni][j] = 0.f;

    load_stage(0, 0);
    load_stage(1, 1);

    const int a_r = lane & 15;
    const int a_c8 = (lane >> 4) * 8;
    const int b_r = lane & 15;

    int st = 0;
    for (int c = 0; c < 32; c++) {
        CP_WAIT1();
        __syncthreads();

        const uint32_t so = sb + st * STG;
#pragma unroll
        for (int kh = 0; kh < 2; kh++) {
            const int kk = kh * 16;
            uint32_t ah[4][4], al[4][4], bf[4][2];
#pragma unroll
            for (int mi = 0; mi < 4; mi++) {
                uint32_t off = (uint32_t)(wm * 64 + mi * 16 + a_r) * 80 +
                               (kk + a_c8) * 2;
                LDSM_X4(ah[mi][0], ah[mi][1], ah[mi][2], ah[mi][3], so + A_HI + off);
                LDSM_X4(al[mi][0], al[mi][1], al[mi][2], al[mi][3], so + A_LO + off);
            }
#pragma unroll
            for (int ni = 0; ni < 4; ni++) {
                uint32_t off = (uint32_t)(kk + b_r) * 272 + (wn * 32 + ni * 8) * 2;
                LDSM_X2T(bf[ni][0], bf[ni][1], so + B_OF + off);
            }
#pragma unroll
            for (int mi = 0; mi < 4; mi++)
#pragma unroll
                for (int ni = 0; ni < 4; ni++) {
                    MMA_F16(acc[mi][ni], ah[mi], bf[ni]);
                    MMA_F16(acc[mi][ni], al[mi], bf[ni]);
                }
        }
        if (c + 2 < 32) load_stage(c + 2, (st + 2 >= NSTAGE) ? st + 2 - NSTAGE : st + 2);
        st = (st + 1 >= NSTAGE) ? 0 : st + 1;
    }

    const int tq = lane >> 2, tr = lane & 3;
#pragma unroll
    for (int mi = 0; mi < 4; mi++) {
        const int r0 = rowBase + wm * 64 + mi * 16 + tq;
        const int r1 = r0 + 8;
        const float bv0 = bias[r0];
        const float bv1 = bias[r1];
        float* p0 = Cb + (size_t)r0 * GN + colBase + wn * 32 + tr * 2;
        float* p1 = Cb + (size_t)r1 * GN + colBase + wn * 32 + tr * 2;
#pragma unroll
        for (int ni = 0; ni < 4; ni++) {
            *(float2*)(p0 + ni * 8) = make_float2(acc[mi][ni][0] + bv0,
                                                  acc[mi][ni][1] + bv0);
            *(float2*)(p1 + ni * 8) = make_float2(acc[mi][ni][2] + bv1,
                                                  acc[mi][ni][3] + bv1);
        }
    }
}

// ---------------------------------------------------------------------------
// Depthwise conv3 (pad 1) + bias + L2-normalize over T (q,k channels only).
// ---------------------------------------------------------------------------
__global__ __launch_bounds__(256) void conv_norm_kernel(
    const float* __restrict__ in, const float* __restrict__ w_dw,
    const float* __restrict__ b_dw, float* __restrict__ out)
{
    __shared__ __align__(16) float s[Tlen + 8];
    __shared__ float red[8];

    const int row = blockIdx.x;
    const int ch  = row % C3;
    const float* inr  = in  + (size_t)row * Tlen;
    float*       outr = out + (size_t)row * Tlen;
    const int tid = threadIdx.x;

    if (tid == 0) { s[3] = 0.f; s[4 + Tlen] = 0.f; }
#pragma unroll
    for (int j = 0; j < 4; j++) {
        int t4 = tid + j * 256;
        *(float4*)&s[4 + t4 * 4] = *(const float4*)(inr + t4 * 4);
    }
    __syncthreads();

    const float w0 = w_dw[ch * 3 + 0];
    const float w1 = w_dw[ch * 3 + 1];
    const float w2 = w_dw[ch * 3 + 2];
    const float bb = b_dw[ch];

    float vals[16];
    float ss = 0.f;
#pragma unroll
    for (int j = 0; j < 4; j++) {
        int t = (tid + j * 256) * 4;
#pragma unroll
        for (int i = 0; i < 4; i++) {
            float v = w0 * s[3 + t + i] + w1 * s[4 + t + i] + w2 * s[5 + t + i] + bb;
            vals[j * 4 + i] = v;
            ss += v * v;
        }
    }

    float scale = 1.f;
    if (ch < 2 * Cch) {
#pragma unroll
        for (int o = 16; o > 0; o >>= 1) ss += __shfl_xor_sync(0xffffffffu, ss, o);
        if ((tid & 31) == 0) red[tid >> 5] = ss;
        __syncthreads();
        if (tid < 32) {
            float r = (tid < 8) ? red[tid] : 0.f;
#pragma unroll
            for (int o = 4; o > 0; o >>= 1) r += __shfl_xor_sync(0xffffffffu, r, o);
            if (tid == 0) red[0] = r;
        }
        __syncthreads();
        float n = sqrtf(red[0]);
        scale = 1.f / fmaxf(n, 1e-12f);
    }

#pragma unroll
    for (int j = 0; j < 4; j++) {
        int t = (tid + j * 256) * 4;
        float4 o4 = make_float4(vals[j * 4 + 0] * scale, vals[j * 4 + 1] * scale,
                                vals[j * 4 + 2] * scale, vals[j * 4 + 3] * scale);
        *(float4*)(outr + t) = o4;
    }
}

// ---------------------------------------------------------------------------
// attn_qk: partial logits over a T-chunk. grid (NCHUNK, B*H).
// ---------------------------------------------------------------------------
__global__ __launch_bounds__(256) void attn_qk(
    const float* __restrict__ conv, float* __restrict__ part)
{
    __shared__ float smA[64][65];
    __shared__ float smB[64][65];

    const int chunk = blockIdx.x;
    const int bh = blockIdx.y;
    const int b = bh >> 4, h = bh & 15;
    const float* qp = conv + ((size_t)b * C3 + h * Dd) * Tlen;
    const float* kp = qp + (size_t)Cch * Tlen;

    const int tid = threadIdx.x;
    const int tx = tid & 15, ty = tid >> 4;

    float acc[4][4];
#pragma unroll
    for (int i = 0; i < 4; i++)
#pragma unroll
        for (int j = 0; j < 4; j++) acc[i][j] = 0.f;

    for (int t0 = chunk * TCH; t0 < (chunk + 1) * TCH; t0 += 64) {
        for (int i = tid; i < 64 * 16; i += 256) {
            int r = i >> 4;
            int c = (i & 15) << 2;
            float4 qv = *(const float4*)(qp + (size_t)r * Tlen + t0 + c);
            float4 kv = *(const float4*)(kp + (size_t)r * Tlen + t0 + c);
            smA[r][c] = qv.x; smA[r][c + 1] = qv.y; smA[r][c + 2] = qv.z; smA[r][c + 3] = qv.w;
            smB[r][c] = kv.x; smB[r][c + 1] = kv.y; smB[r][c + 2] = kv.z; smB[r][c + 3] = kv.w;
        }
        __syncthreads();
#pragma unroll 16
        for (int kk = 0; kk < 64; kk++) {
            float a[4], bv[4];
#pragma unroll
            for (int i = 0; i < 4; i++) a[i]  = smA[ty * 4 + i][kk];
#pragma unroll
            for (int j = 0; j < 4; j++) bv[j] = smB[tx * 4 + j][kk];
#pragma unroll
            for (int i = 0; i < 4; i++)
#pragma unroll
                for (int j = 0; j < 4; j++)
                    acc[i][j] += a[i] * bv[j];
        }
        __syncthreads();
    }

    float* pp = part + ((size_t)bh * NCHUNK + chunk) * 4096;
#pragma unroll
    for (int i = 0; i < 4; i++)
#pragma unroll
        for (int j = 0; j < 4; j++)
            pp[(ty * 4 + i) * 64 + tx * 4 + j] = acc[i][j];
}

// ---------------------------------------------------------------------------
// attn_soft: sum partials, *temp, softmax rows -> attnm[bh][64][64]
// ---------------------------------------------------------------------------
__global__ __launch_bounds__(256) void attn_soft(
    const float* __restrict__ part, const float* __restrict__ temp,
    float* __restrict__ attnm)
{
    __shared__ float sm[64][64];
    const int bh = blockIdx.x;
    const int h = bh & 15;
    const int tid = threadIdx.x;
    const float tsc = temp[h];
    const float* pp = part + (size_t)bh * NCHUNK * 4096;

    for (int i = tid; i < 4096; i += 256) {
        float s = 0.f;
#pragma unroll
        for (int c = 0; c < NCHUNK; c++) s += pp[c * 4096 + i];
        sm[i >> 6][i & 63] = s * tsc;
    }
    __syncthreads();

    const int wid = tid >> 5, lane = tid & 31;
    float* am = attnm + (size_t)bh * 4096;
#pragma unroll
    for (int rr = 0; rr < 8; rr++) {
        const int r = wid * 8 + rr;
        float v0 = sm[r][lane], v1 = sm[r][lane + 32];
        float m = fmaxf(v0, v1);
#pragma unroll
        for (int o = 16; o > 0; o >>= 1) m = fmaxf(m, __shfl_xor_sync(0xffffffffu, m, o));
        float e0 = __expf(v0 - m), e1 = __expf(v1 - m);
        float s = e0 + e1;
#pragma unroll
        for (int o = 16; o > 0; o >>= 1) s += __shfl_xor_sync(0xffffffffu, s, o);
        float inv = 1.f / s;
        am[r * 64 + lane]      = e0 * inv;
        am[r * 64 + lane + 32] = e1 * inv;
    }
}

// ---------------------------------------------------------------------------
// attn_v: out[:, chunk] = A @ v[:, chunk], write fp16 directly. grid (NCHUNK, B*H)
// ---------------------------------------------------------------------------
__global__ __launch_bounds__(256) void attn_v(
    const float* __restrict__ conv, const float* __restrict__ attnm,
    __half* __restrict__ of16)
{
    __shared__ float smA[64][65];
    __shared__ float smB[64][65];

    const int chunk = blockIdx.x;
    const int bh = blockIdx.y;
    const int b = bh >> 4, h = bh & 15;
    const float* vp = conv + ((size_t)b * C3 + 2 * Cch + h * Dd) * Tlen;
    const size_t oBase = ((size_t)b * Cch + h * Dd) * Tlen;

    const int tid = threadIdx.x;
    const int tx = tid & 15, ty = tid >> 4;

    const float* am = attnm + (size_t)bh * 4096;
    for (int i = tid; i < 4096; i += 256)
        smA[i >> 6][i & 63] = am[i];
    __syncthreads();

    for (int t0 = chunk * TCH; t0 < (chunk + 1) * TCH; t0 += 64) {
        for (int i = tid; i < 64 * 16; i += 256) {
            int r = i >> 4;
            int c = (i & 15) << 2;
            float4 vv = *(const float4*)(vp + (size_t)r * Tlen + t0 + c);
            smB[r][c] = vv.x; smB[r][c + 1] = vv.y; smB[r][c + 2] = vv.z; smB[r][c + 3] = vv.w;
        }
        __syncthreads();

        float o4[4][4];
#pragma unroll
        for (int i = 0; i < 4; i++)
#pragma unroll
            for (int j = 0; j < 4; j++) o4[i][j] = 0.f;

#pragma unroll 16
        for (int e = 0; e < 64; e++) {
            float a[4], bv[4];
#pragma unroll
            for (int i = 0; i < 4; i++) a[i]  = smA[ty * 4 + i][e];
#pragma unroll
            for (int j = 0; j < 4; j++) bv[j] = smB[e][tx * 4 + j];
#pragma unroll
            for (int i = 0; i < 4; i++)
#pragma unroll
                for (int j = 0; j < 4; j++)
                    o4[i][j] += a[i] * bv[j];
        }
#pragma unroll
        for (int i = 0; i < 4; i++) {
            size_t off = oBase + (size_t)(ty * 4 + i) * Tlen + t0 + tx * 4;
            __half hv[4];
#pragma unroll
            for (int j = 0; j < 4; j++) hv[j] = __float2half(o4[i][j]);
            *(uint2*)(of16 + off) = *(uint2*)hv;
        }
        __syncthreads();
    }
}

// ---------------------------------------------------------------------------
extern "C" void kernel_launch(void* const* d_in, const int* in_sizes, int n_in,
                              void* d_out, int out_size)
{
    (void)in_sizes; (void)n_in; (void)out_size;
    const float* x     = (const float*)d_in[0];
    const float* w_qkv = (const float*)d_in[1];
    const float* b_qkv = (const float*)d_in[2];
    const float* w_dw  = (const float*)d_in[3];
    const float* b_dw  = (const float*)d_in[4];
    const float* w_out = (const float*)d_in[5];
    const float* b_out = (const float*)d_in[6];
    const float* temp  = (const float*)d_in[7];
    float* out = (float*)d_out;

    float *qkv_buf, *conv_buf;
    __half *xf16, *whi, *wlo;
    cudaGetSymbolAddress((void**)&qkv_buf,  g_qkv);
    cudaGetSymbolAddress((void**)&conv_buf, g_conv);
    cudaGetSymbolAddress((void**)&xf16, g_xf16);
    cudaGetSymbolAddress((void**)&whi, g_whi);
    cudaGetSymbolAddress((void**)&wlo, g_wlo);

    cudaFuncSetAttribute(gemm_mma_f16x2,
                         cudaFuncAttributeMaxDynamicSharedMemorySize, GSMEM);

    const size_t wOutOff = (size_t)C3 * Cch;
    float* part  = qkv_buf;                               // logit scratch (g_qkv reuse)
    float* attnm = qkv_buf + (size_t)128 * NCHUNK * 4096;

    // 1) converts
    cvt_x_f16<<<(Bsz * Cch * Tlen / 4) / 256, 256>>>(x, xf16, Bsz * Cch * Tlen / 4);
    cvt_w_hilo<<<(C3 * Cch / 4) / 256, 256>>>(w_qkv, whi, wlo, C3 * Cch / 4);
    cvt_w_hilo<<<(Cch * Cch / 4) / 256, 256>>>(w_out, whi + wOutOff, wlo + wOutOff,
                                               Cch * Cch / 4);

    // 2) QKV GEMM
    {
        dim3 grid(Tlen / 128, C3 / 128, Bsz);
        gemm_mma_f16x2<<<grid, 256, GSMEM>>>(whi, wlo, xf16, b_qkv, qkv_buf,
                                             (size_t)C3 * Tlen);
    }
    // 3) depthwise conv3 + bias + L2 norm
    conv_norm_kernel<<<Bsz * C3, 256>>>(qkv_buf, w_dw, b_dw, conv_buf);

    // 4) attention, chunked (g_qkv reused as scratch; attn_v emits fp16)
    attn_qk<<<dim3(NCHUNK, Bsz * Hh), 256>>>(conv_buf, part);
    attn_soft<<<Bsz * Hh, 256>>>(part, temp, attnm);
    attn_v<<<dim3(NCHUNK, Bsz * Hh), 256>>>(conv_buf, attnm, xf16);

    // 5) output projection GEMM
    {
        dim3 grid(Tlen / 128, Cch / 128, Bsz);
        gemm_mma_f16x2<<<grid, 256, GSMEM>>>(whi + wOutOff, wlo + wOutOff, xf16,
                                             b_out, out, (size_t)Cch * Tlen);
    }
}

// round 11
// speedup vs baseline: 4.6437x; 1.3623x over previous
#include <cuda_runtime.h>
#include <cuda_fp16.h>
#include <math.h>
#include <stdint.h>

#define Bsz  8
#define Cch  1024
#define Tlen 4096
#define Hh   16
#define Dd   64
#define C3   3072

// ---------------------------------------------------------------------------
// Scratch (allocation-free __device__ globals)
// ---------------------------------------------------------------------------
__device__ float g_qkv[(size_t)Bsz * C3 * Tlen];          // qkv out; later logit scratch
__device__ float g_conv[(size_t)Bsz * C3 * Tlen];         // conv+norm out
__device__ __half g_xf16[(size_t)Bsz * Cch * Tlen];       // activations fp16 (x / attn out)
__device__ __half g_wf16[(size_t)(C3 + Cch) * Cch];       // weights fp16 (qkv|out)

#define NCHUNK 8
#define TCH    (Tlen / NCHUNK)   // 512

// ---------------------------------------------------------------------------
// PTX helpers (sm_80+ portable)
// ---------------------------------------------------------------------------
__device__ __forceinline__ uint32_t s2u(const void* p) {
    uint32_t a;
    asm("{ .reg .u64 t; cvta.to.shared.u64 t, %1; cvt.u32.u64 %0, t; }"
        : "=r"(a) : "l"(p));
    return a;
}

#define CP_ASYNC16(dst, src) \
    asm volatile("cp.async.ca.shared.global [%0], [%1], 16;" \
                 :: "r"(dst), "l"(src) : "memory")
#define CP_COMMIT() asm volatile("cp.async.commit_group;" ::: "memory")
#define CP_WAIT2()  asm volatile("cp.async.wait_group 2;"  ::: "memory")

#define LDSM_X4(r0, r1, r2, r3, addr) \
    asm volatile("ldmatrix.sync.aligned.m8n8.x4.shared.b16 {%0,%1,%2,%3}, [%4];" \
                 : "=r"(r0), "=r"(r1), "=r"(r2), "=r"(r3) : "r"(addr))
#define LDSM_X2T(r0, r1, addr) \
    asm volatile("ldmatrix.sync.aligned.m8n8.x2.trans.shared.b16 {%0,%1}, [%2];" \
                 : "=r"(r0), "=r"(r1) : "r"(addr))

#define MMA_F16(d, a, b) \
    asm volatile("mma.sync.aligned.m16n8k16.row.col.f32.f16.f16.f32 " \
                 "{%0,%1,%2,%3}, {%4,%5,%6,%7}, {%8,%9}, {%0,%1,%2,%3};" \
                 : "+f"((d)[0]), "+f"((d)[1]), "+f"((d)[2]), "+f"((d)[3]) \
                 : "r"((a)[0]), "r"((a)[1]), "r"((a)[2]), "r"((a)[3]), \
                   "r"((b)[0]), "r"((b)[1]))

// ---------------------------------------------------------------------------
// fp32 -> fp16 convert (used for x and weights)
// ---------------------------------------------------------------------------
__global__ __launch_bounds__(256) void cvt_f16(
    const float* __restrict__ in, __half* __restrict__ o, int n4)
{
    int i = blockIdx.x * blockDim.x + threadIdx.x;
    if (i >= n4) return;
    float4 v = ((const float4*)in)[i];
    __half2* op = (__half2*)o;
    op[2 * i]     = __halves2half2(__float2half(v.x), __float2half(v.y));
    op[2 * i + 1] = __halves2half2(__float2half(v.z), __float2half(v.w));
}

// ---------------------------------------------------------------------------
// fp16 GEMM via mma.sync: C[b] = W[M,1024] @ X[b][1024,4096] + bias
// CTA 128x128, BK=32, 256 threads (8 warps, 64x32 each). 4-stage cp.async.
// smem/stage: A[128][40] + B[32][136] halfs = 18944 B
// ---------------------------------------------------------------------------
#define GK   1024
#define GN   4096
#define A_OF 0
#define B_OF 10240
#define STG  18944
#define NSTAGE 4
#define GSMEM (NSTAGE * STG)

__global__ __launch_bounds__(256) void gemm_mma_f16(
    const __half* __restrict__ W, const __half* __restrict__ X,
    const float* __restrict__ bias, float* __restrict__ C, size_t strideC)
{
    extern __shared__ char smem[];
    const uint32_t sb = s2u(smem);
    const int tid  = threadIdx.x;
    const int wid  = tid >> 5;
    const int lane = tid & 31;
    const int wm = wid & 1;
    const int wn = wid >> 1;
    const int rowBase = blockIdx.y * 128;
    const int colBase = blockIdx.x * 128;
    const __half* Xb = X + (size_t)blockIdx.z * GK * GN;
    float* Cb = C + (size_t)blockIdx.z * strideC;

    // per-thread load coords: 2 A-chunks + 2 B-chunks of 16B each
    int a_row[2], a_kq[2], b_row[2], b_nq[2];
#pragma unroll
    for (int i = 0; i < 2; i++) {
        int u = tid + i * 256;
        a_row[i] = u >> 2;  a_kq[i] = u & 3;
        b_row[i] = u >> 4;  b_nq[i] = u & 15;
    }

    auto load_stage = [&](int c, int st) {
        const uint32_t so = sb + st * STG;
        const int k0 = c * 32;
#pragma unroll
        for (int i = 0; i < 2; i++) {
            const __half* srcA = W + (size_t)(rowBase + a_row[i]) * GK + k0 + a_kq[i] * 8;
            CP_ASYNC16(so + A_OF + a_row[i] * 80 + a_kq[i] * 16, srcA);
            const __half* srcB = Xb + (size_t)(k0 + b_row[i]) * GN + colBase + b_nq[i] * 8;
            CP_ASYNC16(so + B_OF + b_row[i] * 272 + b_nq[i] * 16, srcB);
        }
        CP_COMMIT();
    };

    float acc[4][4][4];
#pragma unroll
    for (int mi = 0; mi < 4; mi++)
#pragma unroll
        for (int ni = 0; ni < 4; ni++)
#pragma unroll
            for (int j = 0; j < 4; j++) acc[mi][ni][j] = 0.f;

    load_stage(0, 0);
    load_stage(1, 1);
    load_stage(2, 2);

    const int a_r  = lane & 15;
    const int a_c8 = (lane >> 4) * 8;
    const int b_r  = lane & 15;

    int st = 0;
    for (int c = 0; c < 32; c++) {
        CP_WAIT2();            // stage c resident (3 preloaded, <=2 outstanding)
        __syncthreads();

        const uint32_t so = sb + st * STG;
#pragma unroll
        for (int kh = 0; kh < 2; kh++) {
            const int kk = kh * 16;
            uint32_t af[4][4], bf[4][2];
#pragma unroll
            for (int mi = 0; mi < 4; mi++) {
                uint32_t off = (uint32_t)(wm * 64 + mi * 16 + a_r) * 80 +
                               (kk + a_c8) * 2;
                LDSM_X4(af[mi][0], af[mi][1], af[mi][2], af[mi][3], so + A_OF + off);
            }
#pragma unroll
            for (int ni = 0; ni < 4; ni++) {
                uint32_t off = (uint32_t)(kk + b_r) * 272 + (wn * 32 + ni * 8) * 2;
                LDSM_X2T(bf[ni][0], bf[ni][1], so + B_OF + off);
            }
#pragma unroll
            for (int mi = 0; mi < 4; mi++)
#pragma unroll
                for (int ni = 0; ni < 4; ni++)
                    MMA_F16(acc[mi][ni], af[mi], bf[ni]);
        }
        if (c + 3 < 32) load_stage(c + 3, (st + 3 >= NSTAGE) ? st + 3 - NSTAGE : st + 3);
        st = (st + 1 >= NSTAGE) ? 0 : st + 1;
    }

    const int tq = lane >> 2, tr = lane & 3;
#pragma unroll
    for (int mi = 0; mi < 4; mi++) {
        const int r0 = rowBase + wm * 64 + mi * 16 + tq;
        const int r1 = r0 + 8;
        const float bv0 = bias[r0];
        const float bv1 = bias[r1];
        float* p0 = Cb + (size_t)r0 * GN + colBase + wn * 32 + tr * 2;
        float* p1 = Cb + (size_t)r1 * GN + colBase + wn * 32 + tr * 2;
#pragma unroll
        for (int ni = 0; ni < 4; ni++) {
            *(float2*)(p0 + ni * 8) = make_float2(acc[mi][ni][0] + bv0,
                                                  acc[mi][ni][1] + bv0);
            *(float2*)(p1 + ni * 8) = make_float2(acc[mi][ni][2] + bv1,
                                                  acc[mi][ni][3] + bv1);
        }
    }
}

// ---------------------------------------------------------------------------
// Depthwise conv3 (pad 1) + bias + L2-normalize over T (q,k channels only).
// ---------------------------------------------------------------------------
__global__ __launch_bounds__(256) void conv_norm_kernel(
    const float* __restrict__ in, const float* __restrict__ w_dw,
    const float* __restrict__ b_dw, float* __restrict__ out)
{
    __shared__ __align__(16) float s[Tlen + 8];
    __shared__ float red[8];

    const int row = blockIdx.x;
    const int ch  = row % C3;
    const float* inr  = in  + (size_t)row * Tlen;
    float*       outr = out + (size_t)row * Tlen;
    const int tid = threadIdx.x;

    if (tid == 0) { s[3] = 0.f; s[4 + Tlen] = 0.f; }
#pragma unroll
    for (int j = 0; j < 4; j++) {
        int t4 = tid + j * 256;
        *(float4*)&s[4 + t4 * 4] = *(const float4*)(inr + t4 * 4);
    }
    __syncthreads();

    const float w0 = w_dw[ch * 3 + 0];
    const float w1 = w_dw[ch * 3 + 1];
    const float w2 = w_dw[ch * 3 + 2];
    const float bb = b_dw[ch];

    float vals[16];
    float ss = 0.f;
#pragma unroll
    for (int j = 0; j < 4; j++) {
        int t = (tid + j * 256) * 4;
#pragma unroll
        for (int i = 0; i < 4; i++) {
            float v = w0 * s[3 + t + i] + w1 * s[4 + t + i] + w2 * s[5 + t + i] + bb;
            vals[j * 4 + i] = v;
            ss += v * v;
        }
    }

    float scale = 1.f;
    if (ch < 2 * Cch) {
#pragma unroll
        for (int o = 16; o > 0; o >>= 1) ss += __shfl_xor_sync(0xffffffffu, ss, o);
        if ((tid & 31) == 0) red[tid >> 5] = ss;
        __syncthreads();
        if (tid < 32) {
            float r = (tid < 8) ? red[tid] : 0.f;
#pragma unroll
            for (int o = 4; o > 0; o >>= 1) r += __shfl_xor_sync(0xffffffffu, r, o);
            if (tid == 0) red[0] = r;
        }
        __syncthreads();
        float n = sqrtf(red[0]);
        scale = 1.f / fmaxf(n, 1e-12f);
    }

#pragma unroll
    for (int j = 0; j < 4; j++) {
        int t = (tid + j * 256) * 4;
        float4 o4 = make_float4(vals[j * 4 + 0] * scale, vals[j * 4 + 1] * scale,
                                vals[j * 4 + 2] * scale, vals[j * 4 + 3] * scale);
        *(float4*)(outr + t) = o4;
    }
}

// ---------------------------------------------------------------------------
// attn_qk: partial logits over a T-chunk. grid (NCHUNK, B*H).
// ---------------------------------------------------------------------------
__global__ __launch_bounds__(256) void attn_qk(
    const float* __restrict__ conv, float* __restrict__ part)
{
    __shared__ float smA[64][65];
    __shared__ float smB[64][65];

    const int chunk = blockIdx.x;
    const int bh = blockIdx.y;
    const int b = bh >> 4, h = bh & 15;
    const float* qp = conv + ((size_t)b * C3 + h * Dd) * Tlen;
    const float* kp = qp + (size_t)Cch * Tlen;

    const int tid = threadIdx.x;
    const int tx = tid & 15, ty = tid >> 4;

    float acc[4][4];
#pragma unroll
    for (int i = 0; i < 4; i++)
#pragma unroll
        for (int j = 0; j < 4; j++) acc[i][j] = 0.f;

    for (int t0 = chunk * TCH; t0 < (chunk + 1) * TCH; t0 += 64) {
        for (int i = tid; i < 64 * 16; i += 256) {
            int r = i >> 4;
            int c = (i & 15) << 2;
            float4 qv = *(const float4*)(qp + (size_t)r * Tlen + t0 + c);
            float4 kv = *(const float4*)(kp + (size_t)r * Tlen + t0 + c);
            smA[r][c] = qv.x; smA[r][c + 1] = qv.y; smA[r][c + 2] = qv.z; smA[r][c + 3] = qv.w;
            smB[r][c] = kv.x; smB[r][c + 1] = kv.y; smB[r][c + 2] = kv.z; smB[r][c + 3] = kv.w;
        }
        __syncthreads();
#pragma unroll 16
        for (int kk = 0; kk < 64; kk++) {
            float a[4], bv[4];
#pragma unroll
            for (int i = 0; i < 4; i++) a[i]  = smA[ty * 4 + i][kk];
#pragma unroll
            for (int j = 0; j < 4; j++) bv[j] = smB[tx * 4 + j][kk];
#pragma unroll
            for (int i = 0; i < 4; i++)
#pragma unroll
                for (int j = 0; j < 4; j++)
                    acc[i][j] += a[i] * bv[j];
        }
        __syncthreads();
    }

    float* pp = part + ((size_t)bh * NCHUNK + chunk) * 4096;
#pragma unroll
    for (int i = 0; i < 4; i++)
#pragma unroll
        for (int j = 0; j < 4; j++)
            pp[(ty * 4 + i) * 64 + tx * 4 + j] = acc[i][j];
}

// ---------------------------------------------------------------------------
// attn_soft: sum partials, *temp, softmax rows -> attnm[bh][64][64]
// ---------------------------------------------------------------------------
__global__ __launch_bounds__(256) void attn_soft(
    const float* __restrict__ part, const float* __restrict__ temp,
    float* __restrict__ attnm)
{
    __shared__ float sm[64][64];
    const int bh = blockIdx.x;
    const int h = bh & 15;
    const int tid = threadIdx.x;
    const float tsc = temp[h];
    const float* pp = part + (size_t)bh * NCHUNK * 4096;

    for (int i = tid; i < 4096; i += 256) {
        float s = 0.f;
#pragma unroll
        for (int c = 0; c < NCHUNK; c++) s += pp[c * 4096 + i];
        sm[i >> 6][i & 63] = s * tsc;
    }
    __syncthreads();

    const int wid = tid >> 5, lane = tid & 31;
    float* am = attnm + (size_t)bh * 4096;
#pragma unroll
    for (int rr = 0; rr < 8; rr++) {
        const int r = wid * 8 + rr;
        float v0 = sm[r][lane], v1 = sm[r][lane + 32];
        float m = fmaxf(v0, v1);
#pragma unroll
        for (int o = 16; o > 0; o >>= 1) m = fmaxf(m, __shfl_xor_sync(0xffffffffu, m, o));
        float e0 = __expf(v0 - m), e1 = __expf(v1 - m);
        float s = e0 + e1;
#pragma unroll
        for (int o = 16; o > 0; o >>= 1) s += __shfl_xor_sync(0xffffffffu, s, o);
        float inv = 1.f / s;
        am[r * 64 + lane]      = e0 * inv;
        am[r * 64 + lane + 32] = e1 * inv;
    }
}

// ---------------------------------------------------------------------------
// attn_v: out[:, chunk] = A @ v[:, chunk], write fp16 directly. grid (NCHUNK, B*H)
// ---------------------------------------------------------------------------
__global__ __launch_bounds__(256) void attn_v(
    const float* __restrict__ conv, const float* __restrict__ attnm,
    __half* __restrict__ of16)
{
    __shared__ float smA[64][65];
    __shared__ float smB[64][65];

    const int chunk = blockIdx.x;
    const int bh = blockIdx.y;
    const int b = bh >> 4, h = bh & 15;
    const float* vp = conv + ((size_t)b * C3 + 2 * Cch + h * Dd) * Tlen;
    const size_t oBase = ((size_t)b * Cch + h * Dd) * Tlen;

    const int tid = threadIdx.x;
    const int tx = tid & 15, ty = tid >> 4;

    const float* am = attnm + (size_t)bh * 4096;
    for (int i = tid; i < 4096; i += 256)
        smA[i >> 6][i & 63] = am[i];
    __syncthreads();

    for (int t0 = chunk * TCH; t0 < (chunk + 1) * TCH; t0 += 64) {
        for (int i = tid; i < 64 * 16; i += 256) {
            int r = i >> 4;
            int c = (i & 15) << 2;
            float4 vv = *(const float4*)(vp + (size_t)r * Tlen + t0 + c);
            smB[r][c] = vv.x; smB[r][c + 1] = vv.y; smB[r][c + 2] = vv.z; smB[r][c + 3] = vv.w;
        }
        __syncthreads();

        float o4[4][4];
#pragma unroll
        for (int i = 0; i < 4; i++)
#pragma unroll
            for (int j = 0; j < 4; j++) o4[i][j] = 0.f;

#pragma unroll 16
        for (int e = 0; e < 64; e++) {
            float a[4], bv[4];
#pragma unroll
            for (int i = 0; i < 4; i++) a[i]  = smA[ty * 4 + i][e];
#pragma unroll
            for (int j = 0; j < 4; j++) bv[j] = smB[e][tx * 4 + j];
#pragma unroll
            for (int i = 0; i < 4; i++)
#pragma unroll
                for (int j = 0; j < 4; j++)
                    o4[i][j] += a[i] * bv[j];
        }
#pragma unroll
        for (int i = 0; i < 4; i++) {
            size_t off = oBase + (size_t)(ty * 4 + i) * Tlen + t0 + tx * 4;
            __half hv[4];
#pragma unroll
            for (int j = 0; j < 4; j++) hv[j] = __float2half(o4[i][j]);
            *(uint2*)(of16 + off) = *(uint2*)hv;
        }
        __syncthreads();
    }
}

// ---------------------------------------------------------------------------
extern "C" void kernel_launch(void* const* d_in, const int* in_sizes, int n_in,
                              void* d_out, int out_size)
{
    (void)in_sizes; (void)n_in; (void)out_size;
    const float* x     = (const float*)d_in[0];
    const float* w_qkv = (const float*)d_in[1];
    const float* b_qkv = (const float*)d_in[2];
    const float* w_dw  = (const float*)d_in[3];
    const float* b_dw  = (const float*)d_in[4];
    const float* w_out = (const float*)d_in[5];
    const float* b_out = (const float*)d_in[6];
    const float* temp  = (const float*)d_in[7];
    float* out = (float*)d_out;

    float *qkv_buf, *conv_buf;
    __half *xf16, *wf16;
    cudaGetSymbolAddress((void**)&qkv_buf,  g_qkv);
    cudaGetSymbolAddress((void**)&conv_buf, g_conv);
    cudaGetSymbolAddress((void**)&xf16, g_xf16);
    cudaGetSymbolAddress((void**)&wf16, g_wf16);

    cudaFuncSetAttribute(gemm_mma_f16,
                         cudaFuncAttributeMaxDynamicSharedMemorySize, GSMEM);

    const size_t wOutOff = (size_t)C3 * Cch;
    float* part  = qkv_buf;                               // logit scratch (g_qkv reuse)
    float* attnm = qkv_buf + (size_t)128 * NCHUNK * 4096;

    // 1) converts
    cvt_f16<<<(Bsz * Cch * Tlen / 4) / 256, 256>>>(x, xf16, Bsz * Cch * Tlen / 4);
    cvt_f16<<<(C3 * Cch / 4) / 256, 256>>>(w_qkv, wf16, C3 * Cch / 4);
    cvt_f16<<<(Cch * Cch / 4) / 256, 256>>>(w_out, wf16 + wOutOff, Cch * Cch / 4);

    // 2) QKV GEMM
    {
        dim3 grid(Tlen / 128, C3 / 128, Bsz);
        gemm_mma_f16<<<grid, 256, GSMEM>>>(wf16, xf16, b_qkv, qkv_buf,
                                           (size_t)C3 * Tlen);
    }
    // 3) depthwise conv3 + bias + L2 norm
    conv_norm_kernel<<<Bsz * C3, 256>>>(qkv_buf, w_dw, b_dw, conv_buf);

    // 4) attention, chunked (g_qkv reused as scratch; attn_v emits fp16)
    attn_qk<<<dim3(NCHUNK, Bsz * Hh), 256>>>(conv_buf, part);
    attn_soft<<<Bsz * Hh, 256>>>(part, temp, attnm);
    attn_v<<<dim3(NCHUNK, Bsz * Hh), 256>>>(conv_buf, attnm, xf16);

    // 5) output projection GEMM
    {
        dim3 grid(Tlen / 128, Cch / 128, Bsz);
        gemm_mma_f16<<<grid, 256, GSMEM>>>(wf16 + wOutOff, xf16, b_out, out,
                                           (size_t)Cch * Tlen);
    }
}

// round 12
// speedup vs baseline: 4.6545x; 1.0023x over previous
#include <cuda_runtime.h>
#include <cuda_fp16.h>
#include <math.h>
#include <stdint.h>

#define Bsz  8
#define Cch  1024
#define Tlen 4096
#define Hh   16
#define Dd   64
#define C3   3072

// ---------------------------------------------------------------------------
// Scratch (allocation-free __device__ globals)
// ---------------------------------------------------------------------------
__device__ float g_qkv[(size_t)Bsz * C3 * Tlen];          // qkv out; later logit scratch
__device__ float g_conv[(size_t)Bsz * C3 * Tlen];         // conv+norm out
__device__ __half g_xf16[(size_t)Bsz * Cch * Tlen];       // activations fp16 (x / attn out)
__device__ __half g_wf16[(size_t)(C3 + Cch) * Cch];       // weights fp16 (qkv|out)

#define NCHUNK 8
#define TCH    (Tlen / NCHUNK)   // 512

// ---------------------------------------------------------------------------
// PTX helpers (sm_80+ portable)
// ---------------------------------------------------------------------------
__device__ __forceinline__ uint32_t s2u(const void* p) {
    uint32_t a;
    asm("{ .reg .u64 t; cvta.to.shared.u64 t, %1; cvt.u32.u64 %0, t; }"
        : "=r"(a) : "l"(p));
    return a;
}

#define CP_ASYNC16(dst, src) \
    asm volatile("cp.async.ca.shared.global [%0], [%1], 16;" \
                 :: "r"(dst), "l"(src) : "memory")
#define CP_COMMIT() asm volatile("cp.async.commit_group;" ::: "memory")
#define CP_WAIT2()  asm volatile("cp.async.wait_group 2;"  ::: "memory")

#define LDSM_X4(r0, r1, r2, r3, addr) \
    asm volatile("ldmatrix.sync.aligned.m8n8.x4.shared.b16 {%0,%1,%2,%3}, [%4];" \
                 : "=r"(r0), "=r"(r1), "=r"(r2), "=r"(r3) : "r"(addr))
#define LDSM_X2T(r0, r1, addr) \
    asm volatile("ldmatrix.sync.aligned.m8n8.x2.trans.shared.b16 {%0,%1}, [%2];" \
                 : "=r"(r0), "=r"(r1) : "r"(addr))

#define MMA_F16(d, a, b) \
    asm volatile("mma.sync.aligned.m16n8k16.row.col.f32.f16.f16.f32 " \
                 "{%0,%1,%2,%3}, {%4,%5,%6,%7}, {%8,%9}, {%0,%1,%2,%3};" \
                 : "+f"((d)[0]), "+f"((d)[1]), "+f"((d)[2]), "+f"((d)[3]) \
                 : "r"((a)[0]), "r"((a)[1]), "r"((a)[2]), "r"((a)[3]), \
                   "r"((b)[0]), "r"((b)[1]))

// ---------------------------------------------------------------------------
// fp32 -> fp16 convert (used for x and weights)
// ---------------------------------------------------------------------------
__global__ __launch_bounds__(256) void cvt_f16(
    const float* __restrict__ in, __half* __restrict__ o, int n4)
{
    int i = blockIdx.x * blockDim.x + threadIdx.x;
    if (i >= n4) return;
    float4 v = ((const float4*)in)[i];
    __half2* op = (__half2*)o;
    op[2 * i]     = __halves2half2(__float2half(v.x), __float2half(v.y));
    op[2 * i + 1] = __halves2half2(__float2half(v.z), __float2half(v.w));
}

// ---------------------------------------------------------------------------
// fp16 GEMM via mma.sync: C[b] = W[M,1024] @ X[b][1024,4096] + bias
// CTA 128x128, BK=32, 256 threads (8 warps, 64x32 each). 4-stage cp.async.
// smem/stage: A[128][40] + B[32][136] halfs = 18944 B
// ---------------------------------------------------------------------------
#define GK   1024
#define GN   4096
#define A_OF 0
#define B_OF 10240
#define STG  18944
#define NSTAGE 4
#define GSMEM (NSTAGE * STG)

__global__ __launch_bounds__(256) void gemm_mma_f16(
    const __half* __restrict__ W, const __half* __restrict__ X,
    const float* __restrict__ bias, float* __restrict__ C, size_t strideC)
{
    extern __shared__ char smem[];
    const uint32_t sb = s2u(smem);
    const int tid  = threadIdx.x;
    const int wid  = tid >> 5;
    const int lane = tid & 31;
    const int wm = wid & 1;
    const int wn = wid >> 1;
    const int rowBase = blockIdx.y * 128;
    const int colBase = blockIdx.x * 128;
    const __half* Xb = X + (size_t)blockIdx.z * GK * GN;
    float* Cb = C + (size_t)blockIdx.z * strideC;

    // per-thread load coords: 2 A-chunks + 2 B-chunks of 16B each
    int a_row[2], a_kq[2], b_row[2], b_nq[2];
#pragma unroll
    for (int i = 0; i < 2; i++) {
        int u = tid + i * 256;
        a_row[i] = u >> 2;  a_kq[i] = u & 3;
        b_row[i] = u >> 4;  b_nq[i] = u & 15;
    }

    auto load_stage = [&](int c, int st) {
        const uint32_t so = sb + st * STG;
        const int k0 = c * 32;
#pragma unroll
        for (int i = 0; i < 2; i++) {
            const __half* srcA = W + (size_t)(rowBase + a_row[i]) * GK + k0 + a_kq[i] * 8;
            CP_ASYNC16(so + A_OF + a_row[i] * 80 + a_kq[i] * 16, srcA);
            const __half* srcB = Xb + (size_t)(k0 + b_row[i]) * GN + colBase + b_nq[i] * 8;
            CP_ASYNC16(so + B_OF + b_row[i] * 272 + b_nq[i] * 16, srcB);
        }
        CP_COMMIT();
    };

    float acc[4][4][4];
#pragma unroll
    for (int mi = 0; mi < 4; mi++)
#pragma unroll
        for (int ni = 0; ni < 4; ni++)
#pragma unroll
            for (int j = 0; j < 4; j++) acc[mi][ni][j] = 0.f;

    load_stage(0, 0);
    load_stage(1, 1);
    load_stage(2, 2);

    const int a_r  = lane & 15;
    const int a_c8 = (lane >> 4) * 8;
    const int b_r  = lane & 15;

    int st = 0;
    for (int c = 0; c < 32; c++) {
        CP_WAIT2();            // stage c resident (3 preloaded, <=2 outstanding)
        __syncthreads();

        const uint32_t so = sb + st * STG;
#pragma unroll
        for (int kh = 0; kh < 2; kh++) {
            const int kk = kh * 16;
            uint32_t af[4][4], bf[4][2];
#pragma unroll
            for (int mi = 0; mi < 4; mi++) {
                uint32_t off = (uint32_t)(wm * 64 + mi * 16 + a_r) * 80 +
                               (kk + a_c8) * 2;
                LDSM_X4(af[mi][0], af[mi][1], af[mi][2], af[mi][3], so + A_OF + off);
            }
#pragma unroll
            for (int ni = 0; ni < 4; ni++) {
                uint32_t off = (uint32_t)(kk + b_r) * 272 + (wn * 32 + ni * 8) * 2;
                LDSM_X2T(bf[ni][0], bf[ni][1], so + B_OF + off);
            }
#pragma unroll
            for (int mi = 0; mi < 4; mi++)
#pragma unroll
                for (int ni = 0; ni < 4; ni++)
                    MMA_F16(acc[mi][ni], af[mi], bf[ni]);
        }
        if (c + 3 < 32) load_stage(c + 3, (st + 3 >= NSTAGE) ? st + 3 - NSTAGE : st + 3);
        st = (st + 1 >= NSTAGE) ? 0 : st + 1;
    }

    const int tq = lane >> 2, tr = lane & 3;
#pragma unroll
    for (int mi = 0; mi < 4; mi++) {
        const int r0 = rowBase + wm * 64 + mi * 16 + tq;
        const int r1 = r0 + 8;
        const float bv0 = bias[r0];
        const float bv1 = bias[r1];
        float* p0 = Cb + (size_t)r0 * GN + colBase + wn * 32 + tr * 2;
        float* p1 = Cb + (size_t)r1 * GN + colBase + wn * 32 + tr * 2;
#pragma unroll
        for (int ni = 0; ni < 4; ni++) {
            *(float2*)(p0 + ni * 8) = make_float2(acc[mi][ni][0] + bv0,
                                                  acc[mi][ni][1] + bv0);
            *(float2*)(p1 + ni * 8) = make_float2(acc[mi][ni][2] + bv1,
                                                  acc[mi][ni][3] + bv1);
        }
    }
}

// ---------------------------------------------------------------------------
// Depthwise conv3 (pad 1) + bias + L2-normalize over T (q,k channels only).
// ---------------------------------------------------------------------------
__global__ __launch_bounds__(256) void conv_norm_kernel(
    const float* __restrict__ in, const float* __restrict__ w_dw,
    const float* __restrict__ b_dw, float* __restrict__ out)
{
    __shared__ __align__(16) float s[Tlen + 8];
    __shared__ float red[8];

    const int row = blockIdx.x;
    const int ch  = row % C3;
    const float* inr  = in  + (size_t)row * Tlen;
    float*       outr = out + (size_t)row * Tlen;
    const int tid = threadIdx.x;

    if (tid == 0) { s[3] = 0.f; s[4 + Tlen] = 0.f; }
#pragma unroll
    for (int j = 0; j < 4; j++) {
        int t4 = tid + j * 256;
        *(float4*)&s[4 + t4 * 4] = *(const float4*)(inr + t4 * 4);
    }
    __syncthreads();

    const float w0 = w_dw[ch * 3 + 0];
    const float w1 = w_dw[ch * 3 + 1];
    const float w2 = w_dw[ch * 3 + 2];
    const float bb = b_dw[ch];

    float vals[16];
    float ss = 0.f;
#pragma unroll
    for (int j = 0; j < 4; j++) {
        int t = (tid + j * 256) * 4;
#pragma unroll
        for (int i = 0; i < 4; i++) {
            float v = w0 * s[3 + t + i] + w1 * s[4 + t + i] + w2 * s[5 + t + i] + bb;
            vals[j * 4 + i] = v;
            ss += v * v;
        }
    }

    float scale = 1.f;
    if (ch < 2 * Cch) {
#pragma unroll
        for (int o = 16; o > 0; o >>= 1) ss += __shfl_xor_sync(0xffffffffu, ss, o);
        if ((tid & 31) == 0) red[tid >> 5] = ss;
        __syncthreads();
        if (tid < 32) {
            float r = (tid < 8) ? red[tid] : 0.f;
#pragma unroll
            for (int o = 4; o > 0; o >>= 1) r += __shfl_xor_sync(0xffffffffu, r, o);
            if (tid == 0) red[0] = r;
        }
        __syncthreads();
        float n = sqrtf(red[0]);
        scale = 1.f / fmaxf(n, 1e-12f);
    }

#pragma unroll
    for (int j = 0; j < 4; j++) {
        int t = (tid + j * 256) * 4;
        float4 o4 = make_float4(vals[j * 4 + 0] * scale, vals[j * 4 + 1] * scale,
                                vals[j * 4 + 2] * scale, vals[j * 4 + 3] * scale);
        *(float4*)(outr + t) = o4;
    }
}

// ---------------------------------------------------------------------------
// attn_qk: partial logits over a T-chunk. grid (NCHUNK, B*H).
// ---------------------------------------------------------------------------
__global__ __launch_bounds__(256) void attn_qk(
    const float* __restrict__ conv, float* __restrict__ part)
{
    __shared__ float smA[64][65];
    __shared__ float smB[64][65];

    const int chunk = blockIdx.x;
    const int bh = blockIdx.y;
    const int b = bh >> 4, h = bh & 15;
    const float* qp = conv + ((size_t)b * C3 + h * Dd) * Tlen;
    const float* kp = qp + (size_t)Cch * Tlen;

    const int tid = threadIdx.x;
    const int tx = tid & 15, ty = tid >> 4;

    float acc[4][4];
#pragma unroll
    for (int i = 0; i < 4; i++)
#pragma unroll
        for (int j = 0; j < 4; j++) acc[i][j] = 0.f;

    for (int t0 = chunk * TCH; t0 < (chunk + 1) * TCH; t0 += 64) {
        for (int i = tid; i < 64 * 16; i += 256) {
            int r = i >> 4;
            int c = (i & 15) << 2;
            float4 qv = *(const float4*)(qp + (size_t)r * Tlen + t0 + c);
            float4 kv = *(const float4*)(kp + (size_t)r * Tlen + t0 + c);
            smA[r][c] = qv.x; smA[r][c + 1] = qv.y; smA[r][c + 2] = qv.z; smA[r][c + 3] = qv.w;
            smB[r][c] = kv.x; smB[r][c + 1] = kv.y; smB[r][c + 2] = kv.z; smB[r][c + 3] = kv.w;
        }
        __syncthreads();
#pragma unroll 16
        for (int kk = 0; kk < 64; kk++) {
            float a[4], bv[4];
#pragma unroll
            for (int i = 0; i < 4; i++) a[i]  = smA[ty * 4 + i][kk];
#pragma unroll
            for (int j = 0; j < 4; j++) bv[j] = smB[tx * 4 + j][kk];
#pragma unroll
            for (int i = 0; i < 4; i++)
#pragma unroll
                for (int j = 0; j < 4; j++)
                    acc[i][j] += a[i] * bv[j];
        }
        __syncthreads();
    }

    float* pp = part + ((size_t)bh * NCHUNK + chunk) * 4096;
#pragma unroll
    for (int i = 0; i < 4; i++)
#pragma unroll
        for (int j = 0; j < 4; j++)
            pp[(ty * 4 + i) * 64 + tx * 4 + j] = acc[i][j];
}

// ---------------------------------------------------------------------------
// attn_soft: sum partials, *temp, softmax rows -> attnm[bh][64][64]
// ---------------------------------------------------------------------------
__global__ __launch_bounds__(256) void attn_soft(
    const float* __restrict__ part, const float* __restrict__ temp,
    float* __restrict__ attnm)
{
    __shared__ float sm[64][64];
    const int bh = blockIdx.x;
    const int h = bh & 15;
    const int tid = threadIdx.x;
    const float tsc = temp[h];
    const float* pp = part + (size_t)bh * NCHUNK * 4096;

    for (int i = tid; i < 4096; i += 256) {
        float s = 0.f;
#pragma unroll
        for (int c = 0; c < NCHUNK; c++) s += pp[c * 4096 + i];
        sm[i >> 6][i & 63] = s * tsc;
    }
    __syncthreads();

    const int wid = tid >> 5, lane = tid & 31;
    float* am = attnm + (size_t)bh * 4096;
#pragma unroll
    for (int rr = 0; rr < 8; rr++) {
        const int r = wid * 8 + rr;
        float v0 = sm[r][lane], v1 = sm[r][lane + 32];
        float m = fmaxf(v0, v1);
#pragma unroll
        for (int o = 16; o > 0; o >>= 1) m = fmaxf(m, __shfl_xor_sync(0xffffffffu, m, o));
        float e0 = __expf(v0 - m), e1 = __expf(v1 - m);
        float s = e0 + e1;
#pragma unroll
        for (int o = 16; o > 0; o >>= 1) s += __shfl_xor_sync(0xffffffffu, s, o);
        float inv = 1.f / s;
        am[r * 64 + lane]      = e0 * inv;
        am[r * 64 + lane + 32] = e1 * inv;
    }
}

// ---------------------------------------------------------------------------
// attn_v: out[:, chunk] = A @ v[:, chunk], write fp16 directly. grid (NCHUNK, B*H)
// ---------------------------------------------------------------------------
__global__ __launch_bounds__(256) void attn_v(
    const float* __restrict__ conv, const float* __restrict__ attnm,
    __half* __restrict__ of16)
{
    __shared__ float smA[64][65];
    __shared__ float smB[64][65];

    const int chunk = blockIdx.x;
    const int bh = blockIdx.y;
    const int b = bh >> 4, h = bh & 15;
    const float* vp = conv + ((size_t)b * C3 + 2 * Cch + h * Dd) * Tlen;
    const size_t oBase = ((size_t)b * Cch + h * Dd) * Tlen;

    const int tid = threadIdx.x;
    const int tx = tid & 15, ty = tid >> 4;

    const float* am = attnm + (size_t)bh * 4096;
    for (int i = tid; i < 4096; i += 256)
        smA[i >> 6][i & 63] = am[i];
    __syncthreads();

    for (int t0 = chunk * TCH; t0 < (chunk + 1) * TCH; t0 += 64) {
        for (int i = tid; i < 64 * 16; i += 256) {
            int r = i >> 4;
            int c = (i & 15) << 2;
            float4 vv = *(const float4*)(vp + (size_t)r * Tlen + t0 + c);
            smB[r][c] = vv.x; smB[r][c + 1] = vv.y; smB[r][c + 2] = vv.z; smB[r][c + 3] = vv.w;
        }
        __syncthreads();

        float o4[4][4];
#pragma unroll
        for (int i = 0; i < 4; i++)
#pragma unroll
            for (int j = 0; j < 4; j++) o4[i][j] = 0.f;

#pragma unroll 16
        for (int e = 0; e < 64; e++) {
            float a[4], bv[4];
#pragma unroll
            for (int i = 0; i < 4; i++) a[i]  = smA[ty * 4 + i][e];
#pragma unroll
            for (int j = 0; j < 4; j++) bv[j] = smB[e][tx * 4 + j];
#pragma unroll
            for (int i = 0; i < 4; i++)
#pragma unroll
                for (int j = 0; j < 4; j++)
                    o4[i][j] += a[i] * bv[j];
        }
#pragma unroll
        for (int i = 0; i < 4; i++) {
            size_t off = oBase + (size_t)(ty * 4 + i) * Tlen + t0 + tx * 4;
            __half hv[4];
#pragma unroll
            for (int j = 0; j < 4; j++) hv[j] = __float2half(o4[i][j]);
            *(uint2*)(of16 + off) = *(uint2*)hv;
        }
        __syncthreads();
    }
}

// ---------------------------------------------------------------------------
extern "C" void kernel_launch(void* const* d_in, const int* in_sizes, int n_in,
                              void* d_out, int out_size)
{
    (void)in_sizes; (void)n_in; (void)out_size;
    const float* x     = (const float*)d_in[0];
    const float* w_qkv = (const float*)d_in[1];
    const float* b_qkv = (const float*)d_in[2];
    const float* w_dw  = (const float*)d_in[3];
    const float* b_dw  = (const float*)d_in[4];
    const float* w_out = (const float*)d_in[5];
    const float* b_out = (const float*)d_in[6];
    const float* temp  = (const float*)d_in[7];
    float* out = (float*)d_out;

    float *qkv_buf, *conv_buf;
    __half *xf16, *wf16;
    cudaGetSymbolAddress((void**)&qkv_buf,  g_qkv);
    cudaGetSymbolAddress((void**)&conv_buf, g_conv);
    cudaGetSymbolAddress((void**)&xf16, g_xf16);
    cudaGetSymbolAddress((void**)&wf16, g_wf16);

    cudaFuncSetAttribute(gemm_mma_f16,
                         cudaFuncAttributeMaxDynamicSharedMemorySize, GSMEM);

    const size_t wOutOff = (size_t)C3 * Cch;
    float* part  = qkv_buf;                               // logit scratch (g_qkv reuse)
    float* attnm = qkv_buf + (size_t)128 * NCHUNK * 4096;

    // 1) converts
    cvt_f16<<<(Bsz * Cch * Tlen / 4) / 256, 256>>>(x, xf16, Bsz * Cch * Tlen / 4);
    cvt_f16<<<(C3 * Cch / 4) / 256, 256>>>(w_qkv, wf16, C3 * Cch / 4);
    cvt_f16<<<(Cch * Cch / 4) / 256, 256>>>(w_out, wf16 + wOutOff, Cch * Cch / 4);

    // 2) QKV GEMM
    {
        dim3 grid(Tlen / 128, C3 / 128, Bsz);
        gemm_mma_f16<<<grid, 256, GSMEM>>>(wf16, xf16, b_qkv, qkv_buf,
                                           (size_t)C3 * Tlen);
    }
    // 3) depthwise conv3 + bias + L2 norm
    conv_norm_kernel<<<Bsz * C3, 256>>>(qkv_buf, w_dw, b_dw, conv_buf);

    // 4) attention, chunked (g_qkv reused as scratch; attn_v emits fp16)
    attn_qk<<<dim3(NCHUNK, Bsz * Hh), 256>>>(conv_buf, part);
    attn_soft<<<Bsz * Hh, 256>>>(part, temp, attnm);
    attn_v<<<dim3(NCHUNK, Bsz * Hh), 256>>>(conv_buf, attnm, xf16);

    // 5) output projection GEMM
    {
        dim3 grid(Tlen / 128, Cch / 128, Bsz);
        gemm_mma_f16<<<grid, 256, GSMEM>>>(wf16 + wOutOff, xf16, b_out, out,
                                           (size_t)Cch * Tlen);
    }
}